// round 1
// baseline (speedup 1.0000x reference)
#include <cuda_runtime.h>
#include <cuda_bf16.h>
#include <math.h>

// Problem constants (deterministic per reference)
#define BATCHES   64
#define NODE_DIM  128
#define HIDDEN    256
#define HEADS     8
#define DTOT      2048      // HEADS*HIDDEN
#define N_PAD     96
#define TOTAL_MAX 4128
#define SCALE     0.08838834764831845f   // 1/sqrt(128)

// ---------------- device scratch (static, no allocation) ----------------
__device__ int   g_cnt[BATCHES];
__device__ int   g_start[BATCHES];
__device__ float g_Mt[NODE_DIM * 1024];        // Mt[j][h*128+i] = M_h[i][j]
__device__ float g_P[1024 * NODE_DIM];         // P[(h*128+i)*128 + j] = (Wv_h @ Wo_h)[i][j]
__device__ float g_u[HEADS][NODE_DIM];         // Wq_h @ bk_h
__device__ float g_w2[HEADS][NODE_DIM];        // Wk_h @ bq_h
__device__ float g_cc[HEADS];                  // bq_h . bk_h
__device__ float g_cout[NODE_DIM];             // 96*(bv@Wo + bo)
__device__ float g_Y[TOTAL_MAX * 1024];        // Y[m][h*128+i] = (M_h @ x_m)[i]
__device__ float g_qadd[TOTAL_MAX * HEADS];    // scale*(x_n.u_h + c_h)  == s_pad for query n
__device__ float g_kadd[TOTAL_MAX * HEADS];    // scale*(x_m.w2_h)
__device__ float g_z[BATCHES * 1024];          // z[b][h*128+j]

// ---------------- K0: per-batch counts / starts ----------------
__global__ void k_offsets(const int* __restrict__ batch, int total) {
    __shared__ int cnt[BATCHES];
    int t = threadIdx.x;
    if (t < BATCHES) cnt[t] = 0;
    __syncthreads();
    for (int i = t; i < total; i += blockDim.x) atomicAdd(&cnt[batch[i]], 1);
    __syncthreads();
    if (t == 0) {
        int s = 0;
        for (int b = 0; b < BATCHES; b++) { g_start[b] = s; g_cnt[b] = cnt[b]; s += cnt[b]; }
    }
}

// ---------------- K1a: Mt[j][h*128+i] = sum_t Wq[i,h*256+t]*Wk[j,h*256+t] ----------------
__global__ void k_mt(const float* __restrict__ Wq, const float* __restrict__ Wk) {
    int h = blockIdx.z, i0 = blockIdx.x * 32, j0 = blockIdx.y * 32;
    __shared__ float Aq[32][33];
    __shared__ float Ak[32][33];
    int tid = threadIdx.x;
    int tx = tid & 15, ty = tid >> 4;
    float acc00 = 0, acc01 = 0, acc10 = 0, acc11 = 0;
    for (int t0 = 0; t0 < HIDDEN; t0 += 32) {
        int cc = tid & 31, rb = tid >> 5;
#pragma unroll
        for (int p = 0; p < 4; p++) {
            int r = rb + p * 8;
            Aq[r][cc] = Wq[(i0 + r) * DTOT + h * HIDDEN + t0 + cc];
            Ak[r][cc] = Wk[(j0 + r) * DTOT + h * HIDDEN + t0 + cc];
        }
        __syncthreads();
#pragma unroll
        for (int t = 0; t < 32; t++) {
            float a0 = Aq[tx * 2][t], a1 = Aq[tx * 2 + 1][t];
            float b0 = Ak[ty * 2][t], b1 = Ak[ty * 2 + 1][t];
            acc00 += a0 * b0; acc01 += a0 * b1; acc10 += a1 * b0; acc11 += a1 * b1;
        }
        __syncthreads();
    }
    int i = i0 + tx * 2, j = j0 + ty * 2;
    g_Mt[(j    ) * 1024 + h * 128 + i    ] = acc00;
    g_Mt[(j + 1) * 1024 + h * 128 + i    ] = acc01;
    g_Mt[(j    ) * 1024 + h * 128 + i + 1] = acc10;
    g_Mt[(j + 1) * 1024 + h * 128 + i + 1] = acc11;
}

// ---------------- K1b: P[h][i][j] = sum_t Wv[i,h*256+t]*Wo[h*256+t, j] ----------------
__global__ void k_p(const float* __restrict__ Wv, const float* __restrict__ Wo) {
    int h = blockIdx.z, i0 = blockIdx.x * 32, j0 = blockIdx.y * 32;
    __shared__ float Av[32][33];
    __shared__ float Bo[32][33];
    int tid = threadIdx.x;
    int tx = tid & 15, ty = tid >> 4;
    float acc00 = 0, acc01 = 0, acc10 = 0, acc11 = 0;
    for (int t0 = 0; t0 < HIDDEN; t0 += 32) {
        int cc = tid & 31, rb = tid >> 5;
#pragma unroll
        for (int p = 0; p < 4; p++) {
            int r = rb + p * 8;
            Av[r][cc] = Wv[(i0 + r) * DTOT + h * HIDDEN + t0 + cc];
            Bo[r][cc] = Wo[(h * HIDDEN + t0 + r) * NODE_DIM + j0 + cc];
        }
        __syncthreads();
#pragma unroll
        for (int t = 0; t < 32; t++) {
            float a0 = Av[tx * 2][t], a1 = Av[tx * 2 + 1][t];
            float b0 = Bo[t][ty * 2], b1 = Bo[t][ty * 2 + 1];
            acc00 += a0 * b0; acc01 += a0 * b1; acc10 += a1 * b0; acc11 += a1 * b1;
        }
        __syncthreads();
    }
    int i = i0 + tx * 2, j = j0 + ty * 2;
    g_P[(h * 128 + i    ) * 128 + j    ] = acc00;
    g_P[(h * 128 + i    ) * 128 + j + 1] = acc01;
    g_P[(h * 128 + i + 1) * 128 + j    ] = acc10;
    g_P[(h * 128 + i + 1) * 128 + j + 1] = acc11;
}

// ---------------- K1c: u, w2 (warp per entry) ----------------
__global__ void k_uw(const float* __restrict__ Wq, const float* __restrict__ Wk,
                     const float* __restrict__ bq, const float* __restrict__ bk) {
    int gw = (blockIdx.x * blockDim.x + threadIdx.x) >> 5;
    int lane = threadIdx.x & 31;
    if (gw >= 2048) return;
    int which = gw >> 10;
    int h = (gw >> 7) & 7, i = gw & 127;
    const float* W = which ? Wk : Wq;
    const float* bb = which ? bq : bk;
    float s = 0;
#pragma unroll
    for (int q = 0; q < 8; q++) {
        int k = lane + 32 * q;
        s += W[i * DTOT + h * HIDDEN + k] * bb[h * HIDDEN + k];
    }
#pragma unroll
    for (int o = 16; o; o >>= 1) s += __shfl_xor_sync(0xffffffffu, s, o);
    if (lane == 0) {
        if (which) g_w2[h][i] = s; else g_u[h][i] = s;
    }
}

// ---------------- K1d: c_h and const_out ----------------
__global__ void k_cc(const float* __restrict__ bq, const float* __restrict__ bk,
                     const float* __restrict__ bv, const float* __restrict__ Wo,
                     const float* __restrict__ bo) {
    int t = threadIdx.x;
    if (t < 128) {
        float s = 0;
#pragma unroll 4
        for (int k = 0; k < DTOT; k++) s += bv[k] * Wo[k * NODE_DIM + t];
        g_cout[t] = 96.0f * (s + bo[t]);
    } else if (t < 136) {
        int h = t - 128;
        float s = 0;
        for (int k = 0; k < HIDDEN; k++) s += bq[h * HIDDEN + k] * bk[h * HIDDEN + k];
        g_cc[h] = s;
    }
}

// ---------------- K2: Y[total,1024] = X[total,128] @ Mt[128,1024] ----------------
__global__ void k_y(const float* __restrict__ X, int total) {
    int m0 = blockIdx.x * 64, n0 = blockIdx.y * 64;
    __shared__ float As[16][68];   // padded, 16B-aligned rows for float4
    __shared__ float Bs[16][64];
    int tid = threadIdx.x;
    int tx = tid & 15, ty = tid >> 4;
    float acc[4][4] = {};
    for (int k0 = 0; k0 < NODE_DIM; k0 += 16) {
        {
            int t = tid & 15, mmB = tid >> 4;
#pragma unroll
            for (int p = 0; p < 4; p++) {
                int mm = mmB + 16 * p;
                int m = m0 + mm;
                As[t][mm] = (m < total) ? X[m * NODE_DIM + k0 + t] : 0.0f;
            }
        }
        {
            int nn = tid & 63, tB = tid >> 6;
#pragma unroll
            for (int p = 0; p < 4; p++) {
                int t = tB + 4 * p;
                Bs[t][nn] = g_Mt[(k0 + t) * 1024 + n0 + nn];
            }
        }
        __syncthreads();
#pragma unroll
        for (int t = 0; t < 16; t++) {
            float4 a4 = *reinterpret_cast<const float4*>(&As[t][tx * 4]);
            float4 b4 = *reinterpret_cast<const float4*>(&Bs[t][ty * 4]);
            float a[4] = {a4.x, a4.y, a4.z, a4.w};
            float b[4] = {b4.x, b4.y, b4.z, b4.w};
#pragma unroll
            for (int qa = 0; qa < 4; qa++)
#pragma unroll
                for (int qb = 0; qb < 4; qb++) acc[qa][qb] += a[qa] * b[qb];
        }
        __syncthreads();
    }
#pragma unroll
    for (int qa = 0; qa < 4; qa++) {
        int m = m0 + tx * 4 + qa;
        if (m < total) {
            float4 v = make_float4(acc[qa][0], acc[qa][1], acc[qa][2], acc[qa][3]);
            *reinterpret_cast<float4*>(&g_Y[m * 1024 + n0 + ty * 4]) = v;
        }
    }
}

// ---------------- K2b: qadd / kadd (warp per node) ----------------
__global__ void k_add(const float* __restrict__ X, int total) {
    int warp = (blockIdx.x * blockDim.x + threadIdx.x) >> 5;
    int lane = threadIdx.x & 31;
    if (warp >= total) return;
    float xv[4];
#pragma unroll
    for (int q = 0; q < 4; q++) xv[q] = X[warp * NODE_DIM + lane + 32 * q];
#pragma unroll
    for (int h = 0; h < HEADS; h++) {
        float su = 0, sw = 0;
#pragma unroll
        for (int q = 0; q < 4; q++) {
            su += xv[q] * g_u[h][lane + 32 * q];
            sw += xv[q] * g_w2[h][lane + 32 * q];
        }
#pragma unroll
        for (int o = 16; o; o >>= 1) {
            su += __shfl_xor_sync(0xffffffffu, su, o);
            sw += __shfl_xor_sync(0xffffffffu, sw, o);
        }
        if (lane == 0) {
            g_qadd[warp * HEADS + h] = SCALE * (su + g_cc[h]);
            g_kadd[warp * HEADS + h] = SCALE * sw;
        }
    }
}

// ---------------- K3: attention per (batch, head) -> z ----------------
// smem layout: Ys[128][97] transposed y (conflict-free), Xs[96][128], w[96], qa[96], ka[96]
#define SMEM_ATTN ((128 * 97 + 96 * 128 + 3 * 96) * 4)

__global__ void k_attn(const float* __restrict__ X) {
    int b = blockIdx.x, h = blockIdx.y;
    int c = g_cnt[b], s0 = g_start[b];
    int p = N_PAD - c;
    extern __shared__ float sm[];
    float* Ys = sm;                       // 128*97
    float* Xs = Ys + 128 * 97;            // 96*128
    float* sw = Xs + 96 * 128;            // 96
    float* qa = sw + 96;                  // 96
    float* ka = qa + 96;                  // 96
    int tid = threadIdx.x;

    for (int idx = tid; idx < c * 128; idx += 256) {
        int m = idx >> 7, j = idx & 127;
        Xs[idx] = X[(s0 + m) * NODE_DIM + j];
        Ys[j * 97 + m] = g_Y[(s0 + m) * 1024 + h * 128 + j];
    }
    for (int m = tid; m < N_PAD; m += 256) sw[m] = (m < c) ? (float)p * (1.0f / 96.0f) : 0.0f;
    for (int m = tid; m < c; m += 256) {
        qa[m] = g_qadd[(s0 + m) * HEADS + h];
        ka[m] = g_kadd[(s0 + m) * HEADS + h];
    }
    __syncthreads();

    int warpId = tid >> 5, lane = tid & 31;
    int m0 = lane, m1 = lane + 32, m2 = lane + 64;
    float accW0 = 0, accW1 = 0, accW2 = 0;
    float ka0 = (m0 < c) ? ka[m0] : 0.0f;
    float ka1 = (m1 < c) ? ka[m1] : 0.0f;
    float ka2 = (m2 < c) ? ka[m2] : 0.0f;

    for (int n = warpId; n < c; n += 8) {
        float d0 = 0, d1 = 0, d2 = 0;
        const float4* xr4 = reinterpret_cast<const float4*>(Xs + n * 128);
#pragma unroll 8
        for (int j4 = 0; j4 < 32; j4++) {
            float4 xv = xr4[j4];
            const float* y0 = Ys + (j4 * 4) * 97;
            d0 += xv.x * y0[m0];        d1 += xv.x * y0[m1];        d2 += xv.x * y0[m2];
            d0 += xv.y * y0[97 + m0];   d1 += xv.y * y0[97 + m1];   d2 += xv.y * y0[97 + m2];
            d0 += xv.z * y0[194 + m0];  d1 += xv.z * y0[194 + m1];  d2 += xv.z * y0[194 + m2];
            d0 += xv.w * y0[291 + m0];  d1 += xv.w * y0[291 + m1];  d2 += xv.w * y0[291 + m2];
        }
        float qan = qa[n];
        float s0s = fmaf(SCALE, d0, qan + ka0); if (m0 >= c) s0s = -1e30f;
        float s1s = fmaf(SCALE, d1, qan + ka1); if (m1 >= c) s1s = -1e30f;
        float s2s = fmaf(SCALE, d2, qan + ka2); if (m2 >= c) s2s = -1e30f;
        float mx = fmaxf(fmaxf(s0s, s1s), s2s);
#pragma unroll
        for (int o = 16; o; o >>= 1) mx = fmaxf(mx, __shfl_xor_sync(0xffffffffu, mx, o));
        mx = fmaxf(mx, qan);   // padded-key score
        float e0 = __expf(s0s - mx), e1 = __expf(s1s - mx), e2 = __expf(s2s - mx);
        float se = e0 + e1 + e2;
#pragma unroll
        for (int o = 16; o; o >>= 1) se += __shfl_xor_sync(0xffffffffu, se, o);
        se += (float)p * __expf(qan - mx);
        float inv = 1.0f / se;
        accW0 += e0 * inv; accW1 += e1 * inv; accW2 += e2 * inv;
    }
    if (m0 < c) atomicAdd(&sw[m0], accW0);
    if (m1 < c) atomicAdd(&sw[m1], accW1);
    if (m2 < c) atomicAdd(&sw[m2], accW2);
    __syncthreads();

    if (tid < 128) {
        float z = 0;
        for (int m = 0; m < c; m++) z += sw[m] * Xs[m * 128 + tid];
        g_z[b * 1024 + h * 128 + tid] = z;
    }
}

// ---------------- K4: out[b] = z[b] @ P + const ----------------
__global__ void k_out(float* __restrict__ out) {
    __shared__ float zs[1024];
    int b = blockIdx.x, tid = threadIdx.x;   // 128 threads
    for (int i = tid; i < 1024; i += 128) zs[i] = g_z[b * 1024 + i];
    __syncthreads();
    float acc = g_cout[tid];
#pragma unroll 8
    for (int i = 0; i < 1024; i++) acc += zs[i] * g_P[i * 128 + tid];
    out[b * 128 + tid] = acc;
}

// ---------------- launch ----------------
extern "C" void kernel_launch(void* const* d_in, const int* in_sizes, int n_in,
                              void* d_out, int out_size) {
    const float* x     = (const float*)d_in[0];
    const int*   batch = (const int*)  d_in[1];
    const float* Wq    = (const float*)d_in[2];
    const float* bq    = (const float*)d_in[3];
    const float* Wk    = (const float*)d_in[4];
    const float* bk    = (const float*)d_in[5];
    const float* Wv    = (const float*)d_in[6];
    const float* bv    = (const float*)d_in[7];
    const float* Wo    = (const float*)d_in[8];
    const float* bo    = (const float*)d_in[9];
    float* out = (float*)d_out;
    int total = in_sizes[1];

    cudaFuncSetAttribute(k_attn, cudaFuncAttributeMaxDynamicSharedMemorySize, SMEM_ATTN);

    k_offsets<<<1, 256>>>(batch, total);
    k_mt<<<dim3(4, 4, 8), 256>>>(Wq, Wk);
    k_p <<<dim3(4, 4, 8), 256>>>(Wv, Wo);
    k_uw<<<256, 256>>>(Wq, Wk, bq, bk);
    k_cc<<<1, 256>>>(bq, bk, bv, Wo, bo);
    k_y <<<dim3((total + 63) / 64, 16), 256>>>(x, total);
    k_add<<<(total * 32 + 255) / 256, 256>>>(x, total);
    k_attn<<<dim3(BATCHES, HEADS), 256, SMEM_ATTN>>>(x);
    k_out<<<BATCHES, 128>>>(out);
}

// round 2
// speedup vs baseline: 1.2237x; 1.2237x over previous
#include <cuda_runtime.h>
#include <cuda_bf16.h>
#include <math.h>

#define BATCHES   64
#define NODE_DIM  128
#define HEADS     8
#define HIDDEN    256
#define DTOT      2048
#define N_PAD     96
#define SCALE     0.08838834764831845f   // 1/sqrt(128)

// ---------------- device scratch ----------------
__device__ int   g_cnt[BATCHES];
__device__ int   g_start[BATCHES];
__device__ int   g_order[BATCHES];
__device__ float g_M2[HEADS * 128 * 128];   // M2[h][i][j] = (Wq_h @ Wk_h^T)[i][j]
__device__ float g_P[1024 * 128];           // P[(h*128+i)*128+j] = (Wv_h @ Wo_h)[i][j]
__device__ float g_u[HEADS][128];           // Wq_h @ bk_h
__device__ float g_w2[HEADS][128];          // Wk_h @ bq_h
__device__ float g_cc[HEADS];               // bq_h . bk_h
__device__ float g_cout[128];               // 96*(bv@Wo + bo)
__device__ float g_z[BATCHES * 1024];

// ================= prep kernel: everything input-only =================
__global__ void k_prep(const int* __restrict__ batch,
                       const float* __restrict__ Wq, const float* __restrict__ bq,
                       const float* __restrict__ Wk, const float* __restrict__ bk,
                       const float* __restrict__ Wv, const float* __restrict__ bv,
                       const float* __restrict__ Wo, const float* __restrict__ bo,
                       int total) {
    int bid = blockIdx.x;
    int tid = threadIdx.x;

    if (bid == 0) {
        // ---- counts / starts / order (sorted desc by count) ----
        __shared__ int cnt[BATCHES];
        if (tid < BATCHES) cnt[tid] = 0;
        __syncthreads();
        for (int i = tid; i < total; i += 256) atomicAdd(&cnt[batch[i]], 1);
        __syncthreads();
        if (tid == 0) {
            int s = 0;
            int ord[BATCHES];
            for (int b = 0; b < BATCHES; b++) {
                g_start[b] = s; g_cnt[b] = cnt[b]; s += cnt[b];
                ord[b] = b;
            }
            // selection sort desc by count
            for (int i = 0; i < BATCHES - 1; i++) {
                int best = i;
                for (int j = i + 1; j < BATCHES; j++)
                    if (cnt[ord[j]] > cnt[ord[best]]) best = j;
                int t = ord[i]; ord[i] = ord[best]; ord[best] = t;
            }
            for (int b = 0; b < BATCHES; b++) g_order[b] = ord[b];
        }
        return;
    }
    if (bid == 1) {
        // ---- cout and cc ----
        if (tid < 128) {
            float s = 0.f;
#pragma unroll 4
            for (int k = 0; k < DTOT; k++) s = fmaf(bv[k], Wo[k * 128 + tid], s);
            g_cout[tid] = 96.0f * (s + bo[tid]);
        } else if (tid < 136) {
            int h = tid - 128;
            float s = 0.f;
            for (int k = 0; k < HIDDEN; k++) s = fmaf(bq[h * HIDDEN + k], bk[h * HIDDEN + k], s);
            g_cc[h] = s;
        }
        return;
    }
    if (bid < 258) {
        // ---- u[h][i] = Wq_h[i]·bk_h ; w2[h][i] = Wk_h[i]·bq_h ----
        int gw = (bid - 2) * 8 + (tid >> 5);
        int lane = tid & 31;
        int which = gw >> 10;             // 0: u, 1: w2
        int h = (gw >> 7) & 7, i = gw & 127;
        const float* W  = which ? Wk : Wq;
        const float* bb = which ? bq : bk;
        float s = 0.f;
#pragma unroll
        for (int q = 0; q < 8; q++) {
            int k = lane + 32 * q;
            s = fmaf(W[i * DTOT + h * HIDDEN + k], bb[h * HIDDEN + k], s);
        }
#pragma unroll
        for (int o = 16; o; o >>= 1) s += __shfl_xor_sync(0xffffffffu, s, o);
        if (lane == 0) {
            if (which) g_w2[h][i] = s; else g_u[h][i] = s;
        }
        return;
    }
    // ---- M2 (bid 258..385) or P (bid 386..513): 32x32 tiles ----
    bool doP = (bid >= 386);
    int q = bid - (doP ? 386 : 258);
    int h = q >> 4;
    int i0 = ((q >> 2) & 3) * 32, j0 = (q & 3) * 32;
    __shared__ float As[32][33];
    __shared__ float Bs[32][33];
    int tx = tid & 15, ty = tid >> 4;
    float a00 = 0, a01 = 0, a10 = 0, a11 = 0;
    for (int t0 = 0; t0 < HIDDEN; t0 += 32) {
        int cc = tid & 31, rb = tid >> 5;
#pragma unroll
        for (int p = 0; p < 4; p++) {
            int r = rb + p * 8;
            if (!doP) {
                As[r][cc] = Wq[(i0 + r) * DTOT + h * HIDDEN + t0 + cc];
                Bs[r][cc] = Wk[(j0 + r) * DTOT + h * HIDDEN + t0 + cc];
            } else {
                As[r][cc] = Wv[(i0 + r) * DTOT + h * HIDDEN + t0 + cc];
                Bs[r][cc] = Wo[(h * HIDDEN + t0 + r) * 128 + j0 + cc];
            }
        }
        __syncthreads();
        if (!doP) {
#pragma unroll
            for (int t = 0; t < 32; t++) {
                float x0 = As[tx * 2][t], x1 = As[tx * 2 + 1][t];
                float y0 = Bs[ty * 2][t], y1 = Bs[ty * 2 + 1][t];
                a00 = fmaf(x0, y0, a00); a01 = fmaf(x0, y1, a01);
                a10 = fmaf(x1, y0, a10); a11 = fmaf(x1, y1, a11);
            }
        } else {
#pragma unroll
            for (int t = 0; t < 32; t++) {
                float x0 = As[tx * 2][t], x1 = As[tx * 2 + 1][t];
                float y0 = Bs[t][ty * 2], y1 = Bs[t][ty * 2 + 1];
                a00 = fmaf(x0, y0, a00); a01 = fmaf(x0, y1, a01);
                a10 = fmaf(x1, y0, a10); a11 = fmaf(x1, y1, a11);
            }
        }
        __syncthreads();
    }
    int i = i0 + tx * 2, j = j0 + ty * 2;
    float* dst = doP ? g_P : g_M2;
    dst[(h * 128 + i    ) * 128 + j    ] = a00;
    dst[(h * 128 + i    ) * 128 + j + 1] = a01;
    dst[(h * 128 + i + 1) * 128 + j    ] = a10;
    dst[(h * 128 + i + 1) * 128 + j + 1] = a11;
}

// ================= fused attention kernel =================
// smem: Xt[128][97] + Tt[128][97] + Msub[16][128] + sw[96]+qa[96]+ka[96]
#define XT_F   (128 * 97)
#define SMEM_F (2 * XT_F + 16 * 128 + 3 * 96)
#define SMEM_B (SMEM_F * 4)

template <int R>
__device__ __forceinline__ void attn_core(
    int tid, int c, int h, float pcount,
    float* __restrict__ Xt, float* __restrict__ Tt, float* __restrict__ Msub,
    float* __restrict__ sw, const float* __restrict__ qa, const float* __restrict__ ka)
{
    const int warp = tid >> 5, lane = tid & 31;
    const int n0 = warp * R;
    const float* Mg = g_M2 + (h << 14);

    // ---------- GEMM1: T[n][j] = sum_i Xt[i][n] * M[i][j] ----------
    float acc[R][4];
#pragma unroll
    for (int r = 0; r < R; r++)
#pragma unroll
        for (int q = 0; q < 4; q++) acc[r][q] = 0.f;

    const int lrow = tid >> 4;            // 0..15
    const int lcol = (tid & 15) << 3;     // 0..120
    float4 p0 = *reinterpret_cast<const float4*>(Mg + lrow * 128 + lcol);
    float4 p1 = *reinterpret_cast<const float4*>(Mg + lrow * 128 + lcol + 4);

    for (int kc = 0; kc < 8; kc++) {
        __syncthreads();
        *reinterpret_cast<float4*>(Msub + lrow * 128 + lcol)     = p0;
        *reinterpret_cast<float4*>(Msub + lrow * 128 + lcol + 4) = p1;
        __syncthreads();
        if (kc < 7) {
            p0 = *reinterpret_cast<const float4*>(Mg + ((kc + 1) * 16 + lrow) * 128 + lcol);
            p1 = *reinterpret_cast<const float4*>(Mg + ((kc + 1) * 16 + lrow) * 128 + lcol + 4);
        }
        const float* XtI = Xt + (kc * 16) * 97 + n0;
#pragma unroll
        for (int ii = 0; ii < 16; ii++) {
            float mv0 = Msub[ii * 128 + lane];
            float mv1 = Msub[ii * 128 + lane + 32];
            float mv2 = Msub[ii * 128 + lane + 64];
            float mv3 = Msub[ii * 128 + lane + 96];
#pragma unroll
            for (int r = 0; r < R; r++) {
                float xv = XtI[ii * 97 + r];
                acc[r][0] = fmaf(xv, mv0, acc[r][0]);
                acc[r][1] = fmaf(xv, mv1, acc[r][1]);
                acc[r][2] = fmaf(xv, mv2, acc[r][2]);
                acc[r][3] = fmaf(xv, mv3, acc[r][3]);
            }
        }
    }
#pragma unroll
    for (int r = 0; r < R; r++) {
        Tt[(lane     ) * 97 + n0 + r] = acc[r][0];
        Tt[(lane + 32) * 97 + n0 + r] = acc[r][1];
        Tt[(lane + 64) * 97 + n0 + r] = acc[r][2];
        Tt[(lane + 96) * 97 + n0 + r] = acc[r][3];
    }
    __syncthreads();

    // ---------- GEMM2: S[n][m] = sum_j T[n][j] * Xt[j][m] ----------
    const int m0 = lane, m1 = lane + 32, m2 = lane + 64;
    float d0[R], d1[R], d2[R];
#pragma unroll
    for (int r = 0; r < R; r++) { d0[r] = 0.f; d1[r] = 0.f; d2[r] = 0.f; }
#pragma unroll 4
    for (int j = 0; j < 128; j++) {
        float x0 = Xt[j * 97 + m0];
        float x1 = Xt[j * 97 + m1];
        float x2 = Xt[j * 97 + m2];
        const float* Tr = Tt + j * 97 + n0;
#pragma unroll
        for (int r = 0; r < R; r++) {
            float tv = Tr[r];
            d0[r] = fmaf(tv, x0, d0[r]);
            d1[r] = fmaf(tv, x1, d1[r]);
            d2[r] = fmaf(tv, x2, d2[r]);
        }
    }

    // ---------- softmax + key-mass accumulation ----------
    float ka0 = (m0 < c) ? ka[m0] : 0.f;
    float ka1 = (m1 < c) ? ka[m1] : 0.f;
    float ka2 = (m2 < c) ? ka[m2] : 0.f;
    float aW0 = 0.f, aW1 = 0.f, aW2 = 0.f;
#pragma unroll
    for (int r = 0; r < R; r++) {
        int n = n0 + r;
        if (n < c) {                       // uniform across warp
            float qan = qa[n];
            float s0 = (m0 < c) ? fmaf(SCALE, d0[r], qan + ka0) : -1e30f;
            float s1 = (m1 < c) ? fmaf(SCALE, d1[r], qan + ka1) : -1e30f;
            float s2 = (m2 < c) ? fmaf(SCALE, d2[r], qan + ka2) : -1e30f;
            float mx = fmaxf(qan, fmaxf(s0, fmaxf(s1, s2)));
#pragma unroll
            for (int o = 16; o; o >>= 1) mx = fmaxf(mx, __shfl_xor_sync(0xffffffffu, mx, o));
            float e0 = __expf(s0 - mx), e1 = __expf(s1 - mx), e2 = __expf(s2 - mx);
            float se = e0 + e1 + e2;
#pragma unroll
            for (int o = 16; o; o >>= 1) se += __shfl_xor_sync(0xffffffffu, se, o);
            se += pcount * __expf(qan - mx);
            float inv = 1.0f / se;
            aW0 = fmaf(e0, inv, aW0);
            aW1 = fmaf(e1, inv, aW1);
            aW2 = fmaf(e2, inv, aW2);
        }
    }
    if (m0 < c) atomicAdd(&sw[m0], aW0);
    if (m1 < c) atomicAdd(&sw[m1], aW1);
    if (m2 < c) atomicAdd(&sw[m2], aW2);
}

__global__ void __launch_bounds__(256) k_attn(const float* __restrict__ X) {
    int b = g_order[blockIdx.x];
    int h = blockIdx.y;
    int c = g_cnt[b];
    int st = g_start[b];
    float pcount = (float)(N_PAD - c);
    extern __shared__ float sm[];
    float* Xt   = sm;
    float* Tt   = sm + XT_F;
    float* Msub = sm + 2 * XT_F;
    float* sw   = Msub + 16 * 128;
    float* qa   = sw + 96;
    float* ka   = qa + 96;
    int tid = threadIdx.x;

    // load X transposed (zero-pad invalid columns)
    for (int idx = tid; idx < 96 * 128; idx += 256) {
        int m = idx >> 7, j = idx & 127;
        Xt[j * 97 + m] = (m < c) ? X[(st + m) * 128 + j] : 0.f;
    }
    if (tid < 96) sw[tid] = (tid < c) ? pcount * (1.0f / 96.0f) : 0.f;
    __syncthreads();

    // per-node bias terms
    if (tid < c) {
        float qacc = 0.f, kacc = 0.f;
#pragma unroll 4
        for (int i = 0; i < 128; i++) {
            float xv = Xt[i * 97 + tid];
            qacc = fmaf(xv, g_u[h][i], qacc);
            kacc = fmaf(xv, g_w2[h][i], kacc);
        }
        qa[tid] = SCALE * (qacc + g_cc[h]);
        ka[tid] = SCALE * kacc;
    }

    int rpw = (c + 7) >> 3;   // 4..12
    switch (rpw) {
        case 4:  attn_core<4 >(tid, c, h, pcount, Xt, Tt, Msub, sw, qa, ka); break;
        case 5:  attn_core<5 >(tid, c, h, pcount, Xt, Tt, Msub, sw, qa, ka); break;
        case 6:  attn_core<6 >(tid, c, h, pcount, Xt, Tt, Msub, sw, qa, ka); break;
        case 7:  attn_core<7 >(tid, c, h, pcount, Xt, Tt, Msub, sw, qa, ka); break;
        case 8:  attn_core<8 >(tid, c, h, pcount, Xt, Tt, Msub, sw, qa, ka); break;
        case 9:  attn_core<9 >(tid, c, h, pcount, Xt, Tt, Msub, sw, qa, ka); break;
        case 10: attn_core<10>(tid, c, h, pcount, Xt, Tt, Msub, sw, qa, ka); break;
        case 11: attn_core<11>(tid, c, h, pcount, Xt, Tt, Msub, sw, qa, ka); break;
        default: attn_core<12>(tid, c, h, pcount, Xt, Tt, Msub, sw, qa, ka); break;
    }
    __syncthreads();

    // z[i] = sum_m sw[m] * x_m[i]
    if (tid < 128) {
        float z = 0.f;
        for (int m = 0; m < c; m++) z = fmaf(sw[m], Xt[tid * 97 + m], z);
        g_z[(b << 10) + (h << 7) + tid] = z;
    }
}

// ================= output projection =================
__global__ void k_out(float* __restrict__ out) {
    __shared__ float zs[1024];
    int b = blockIdx.x, tid = threadIdx.x;   // 128 threads
    for (int i = tid; i < 1024; i += 128) zs[i] = g_z[b * 1024 + i];
    __syncthreads();
    float acc = g_cout[tid];
#pragma unroll 8
    for (int i = 0; i < 1024; i++) acc = fmaf(zs[i], g_P[i * 128 + tid], acc);
    out[b * 128 + tid] = acc;
}

// ================= launch =================
extern "C" void kernel_launch(void* const* d_in, const int* in_sizes, int n_in,
                              void* d_out, int out_size) {
    const float* x     = (const float*)d_in[0];
    const int*   batch = (const int*)  d_in[1];
    const float* Wq    = (const float*)d_in[2];
    const float* bq    = (const float*)d_in[3];
    const float* Wk    = (const float*)d_in[4];
    const float* bk    = (const float*)d_in[5];
    const float* Wv    = (const float*)d_in[6];
    const float* bv    = (const float*)d_in[7];
    const float* Wo    = (const float*)d_in[8];
    const float* bo    = (const float*)d_in[9];
    float* out = (float*)d_out;
    int total = in_sizes[1];

    cudaFuncSetAttribute(k_attn, cudaFuncAttributeMaxDynamicSharedMemorySize, SMEM_B);

    k_prep<<<514, 256>>>(batch, Wq, bq, Wk, bk, Wv, bv, Wo, bo, total);
    k_attn<<<dim3(BATCHES, HEADS), 256, SMEM_B>>>(x);
    k_out<<<BATCHES, 128>>>(out);
}

// round 3
// speedup vs baseline: 1.8544x; 1.5155x over previous
#include <cuda_runtime.h>
#include <cuda_bf16.h>
#include <math.h>

#define BATCHES   64
#define NODE_DIM  128
#define HEADS     8
#define HIDDEN    256
#define DTOT      2048
#define N_PAD     96
#define SCALE     0.08838834764831845f   // 1/sqrt(128)

// ---------------- device scratch ----------------
__device__ int   g_cnt[BATCHES];
__device__ int   g_start[BATCHES];
__device__ int   g_order[BATCHES];
__device__ float g_M2[HEADS * 128 * 128];   // M2[h][i][j] = (Wq_h @ Wk_h^T)[i][j]
__device__ float g_P[1024 * 128];           // P[(h*128+i)*128+j] = (Wv_h @ Wo_h)[i][j]
__device__ float g_u[HEADS][128];           // Wq_h @ bk_h
__device__ float g_w2[HEADS][128];          // Wk_h @ bq_h
__device__ float g_cc[HEADS];               // bq_h . bk_h
__device__ float g_cout_part[16][128];      // partials of bv @ Wo over k-chunks
__device__ float g_z[BATCHES * 1024];

// ================= prep kernel =================
// grid layout:
//   bid 0        : counts/starts (boundary scan) + parallel rank sort
//   bid 1        : cc[h] (warp per head)
//   bid 2..257   : u / w2 (warp per output element)
//   bid 258..385 : M2 32x32 tiles
//   bid 386..513 : P  32x32 tiles
//   bid 514..521 : cout partials (k-chunks of 256)
__global__ void k_prep(const int* __restrict__ batch,
                       const float* __restrict__ Wq, const float* __restrict__ bq,
                       const float* __restrict__ Wk, const float* __restrict__ bk,
                       const float* __restrict__ Wv, const float* __restrict__ bv,
                       const float* __restrict__ Wo, const float* __restrict__ bo,
                       int total) {
    int bid = blockIdx.x;
    int tid = threadIdx.x;

    if (bid == 0) {
        // ---- segment ends via boundary scan (batch is sorted) ----
        __shared__ int ends[BATCHES];
        __shared__ int cnt[BATCHES];
        for (int i = tid; i < total; i += 256) {
            int bcur = batch[i];
            int bnxt = (i + 1 < total) ? batch[i + 1] : -1;
            if (bcur != bnxt) ends[bcur] = i + 1;
        }
        __syncthreads();
        if (tid < BATCHES) {
            int e = ends[tid];
            int s = (tid > 0) ? ends[tid - 1] : 0;
            g_start[tid] = s;
            cnt[tid] = e - s;
            g_cnt[tid] = e - s;
        }
        __syncthreads();
        if (tid < BATCHES) {
            // parallel rank: desc by count, asc by index for ties
            int myc = cnt[tid];
            int rank = 0;
#pragma unroll 8
            for (int b = 0; b < BATCHES; b++) {
                int cb = cnt[b];
                rank += (cb > myc) || (cb == myc && b < tid);
            }
            g_order[rank] = tid;
        }
        return;
    }
    if (bid == 1) {
        // ---- cc[h] = bq_h . bk_h (warp per head) ----
        int h = tid >> 5, lane = tid & 31;
        float s = 0.f;
#pragma unroll
        for (int q = 0; q < 8; q++) {
            int k = h * HIDDEN + lane + 32 * q;
            s = fmaf(bq[k], bk[k], s);
        }
#pragma unroll
        for (int o = 16; o; o >>= 1) s += __shfl_xor_sync(0xffffffffu, s, o);
        if (lane == 0) g_cc[h] = s;
        return;
    }
    if (bid < 258) {
        // ---- u[h][i] = Wq_h[i]·bk_h ; w2[h][i] = Wk_h[i]·bq_h ----
        int gw = (bid - 2) * 8 + (tid >> 5);
        int lane = tid & 31;
        int which = gw >> 10;             // 0: u, 1: w2
        int h = (gw >> 7) & 7, i = gw & 127;
        const float* W  = which ? Wk : Wq;
        const float* bb = which ? bq : bk;
        float s = 0.f;
#pragma unroll
        for (int q = 0; q < 8; q++) {
            int k = lane + 32 * q;
            s = fmaf(W[i * DTOT + h * HIDDEN + k], bb[h * HIDDEN + k], s);
        }
#pragma unroll
        for (int o = 16; o; o >>= 1) s += __shfl_xor_sync(0xffffffffu, s, o);
        if (lane == 0) {
            if (which) g_w2[h][i] = s; else g_u[h][i] = s;
        }
        return;
    }
    if (bid >= 514) {
        // ---- cout partials: chunk p covers k in [p*256, p*256+256) ----
        int p = bid - 514;                // 0..7
        int j = tid & 127;
        int half = tid >> 7;              // 0/1
        int k0 = p * 256 + half * 128;
        float s = 0.f;
#pragma unroll 8
        for (int kk = 0; kk < 128; kk++) {
            int k = k0 + kk;
            s = fmaf(bv[k], Wo[k * 128 + j], s);
        }
        g_cout_part[p * 2 + half][j] = s;
        return;
    }
    // ---- M2 (bid 258..385) or P (bid 386..513): 32x32 tiles ----
    bool doP = (bid >= 386);
    int q = bid - (doP ? 386 : 258);
    int h = q >> 4;
    int i0 = ((q >> 2) & 3) * 32, j0 = (q & 3) * 32;
    __shared__ float As[32][33];
    __shared__ float Bs[32][33];
    int tx = tid & 15, ty = tid >> 4;
    float a00 = 0, a01 = 0, a10 = 0, a11 = 0;
    for (int t0 = 0; t0 < HIDDEN; t0 += 32) {
        int cc = tid & 31, rb = tid >> 5;
#pragma unroll
        for (int p = 0; p < 4; p++) {
            int r = rb + p * 8;
            if (!doP) {
                As[r][cc] = Wq[(i0 + r) * DTOT + h * HIDDEN + t0 + cc];
                Bs[r][cc] = Wk[(j0 + r) * DTOT + h * HIDDEN + t0 + cc];
            } else {
                As[r][cc] = Wv[(i0 + r) * DTOT + h * HIDDEN + t0 + cc];
                Bs[r][cc] = Wo[(h * HIDDEN + t0 + r) * 128 + j0 + cc];
            }
        }
        __syncthreads();
        if (!doP) {
#pragma unroll
            for (int t = 0; t < 32; t++) {
                float x0 = As[tx * 2][t], x1 = As[tx * 2 + 1][t];
                float y0 = Bs[ty * 2][t], y1 = Bs[ty * 2 + 1][t];
                a00 = fmaf(x0, y0, a00); a01 = fmaf(x0, y1, a01);
                a10 = fmaf(x1, y0, a10); a11 = fmaf(x1, y1, a11);
            }
        } else {
#pragma unroll
            for (int t = 0; t < 32; t++) {
                float x0 = As[tx * 2][t], x1 = As[tx * 2 + 1][t];
                float y0 = Bs[t][ty * 2], y1 = Bs[t][ty * 2 + 1];
                a00 = fmaf(x0, y0, a00); a01 = fmaf(x0, y1, a01);
                a10 = fmaf(x1, y0, a10); a11 = fmaf(x1, y1, a11);
            }
        }
        __syncthreads();
    }
    int i = i0 + tx * 2, j = j0 + ty * 2;
    float* dst = doP ? g_P : g_M2;
    dst[(h * 128 + i    ) * 128 + j    ] = a00;
    dst[(h * 128 + i    ) * 128 + j + 1] = a01;
    dst[(h * 128 + i + 1) * 128 + j    ] = a10;
    dst[(h * 128 + i + 1) * 128 + j + 1] = a11;
}

// ================= fused attention kernel =================
// smem: Xt[128][97] + Tt[128][97] + Msub[16][128] + sw[96]+qa[96]+ka[96]
#define XT_F   (128 * 97)
#define SMEM_F (2 * XT_F + 16 * 128 + 3 * 96)
#define SMEM_B (SMEM_F * 4)

template <int R>
__device__ __forceinline__ void attn_core(
    int tid, int c, int h, float pcount,
    float* __restrict__ Xt, float* __restrict__ Tt, float* __restrict__ Msub,
    float* __restrict__ sw, const float* __restrict__ qa, const float* __restrict__ ka)
{
    const int warp = tid >> 5, lane = tid & 31;
    const int n0 = warp * R;
    const float* Mg = g_M2 + (h << 14);

    // ---------- GEMM1: T[n][j] = sum_i Xt[i][n] * M[i][j] ----------
    float acc[R][4];
#pragma unroll
    for (int r = 0; r < R; r++)
#pragma unroll
        for (int q = 0; q < 4; q++) acc[r][q] = 0.f;

    const int lrow = tid >> 4;            // 0..15
    const int lcol = (tid & 15) << 3;     // 0..120
    float4 p0 = *reinterpret_cast<const float4*>(Mg + lrow * 128 + lcol);
    float4 p1 = *reinterpret_cast<const float4*>(Mg + lrow * 128 + lcol + 4);

    for (int kc = 0; kc < 8; kc++) {
        __syncthreads();
        *reinterpret_cast<float4*>(Msub + lrow * 128 + lcol)     = p0;
        *reinterpret_cast<float4*>(Msub + lrow * 128 + lcol + 4) = p1;
        __syncthreads();
        if (kc < 7) {
            p0 = *reinterpret_cast<const float4*>(Mg + ((kc + 1) * 16 + lrow) * 128 + lcol);
            p1 = *reinterpret_cast<const float4*>(Mg + ((kc + 1) * 16 + lrow) * 128 + lcol + 4);
        }
        const float* XtI = Xt + (kc * 16) * 97 + n0;
#pragma unroll
        for (int ii = 0; ii < 16; ii++) {
            float mv0 = Msub[ii * 128 + lane];
            float mv1 = Msub[ii * 128 + lane + 32];
            float mv2 = Msub[ii * 128 + lane + 64];
            float mv3 = Msub[ii * 128 + lane + 96];
#pragma unroll
            for (int r = 0; r < R; r++) {
                float xv = XtI[ii * 97 + r];
                acc[r][0] = fmaf(xv, mv0, acc[r][0]);
                acc[r][1] = fmaf(xv, mv1, acc[r][1]);
                acc[r][2] = fmaf(xv, mv2, acc[r][2]);
                acc[r][3] = fmaf(xv, mv3, acc[r][3]);
            }
        }
    }
#pragma unroll
    for (int r = 0; r < R; r++) {
        Tt[(lane     ) * 97 + n0 + r] = acc[r][0];
        Tt[(lane + 32) * 97 + n0 + r] = acc[r][1];
        Tt[(lane + 64) * 97 + n0 + r] = acc[r][2];
        Tt[(lane + 96) * 97 + n0 + r] = acc[r][3];
    }
    __syncthreads();

    // ---------- GEMM2: S[n][m] = sum_j T[n][j] * Xt[j][m] ----------
    const int m0 = lane, m1 = lane + 32, m2 = lane + 64;
    float d0[R], d1[R], d2[R];
#pragma unroll
    for (int r = 0; r < R; r++) { d0[r] = 0.f; d1[r] = 0.f; d2[r] = 0.f; }
#pragma unroll 4
    for (int j = 0; j < 128; j++) {
        float x0 = Xt[j * 97 + m0];
        float x1 = Xt[j * 97 + m1];
        float x2 = Xt[j * 97 + m2];
        const float* Tr = Tt + j * 97 + n0;
#pragma unroll
        for (int r = 0; r < R; r++) {
            float tv = Tr[r];
            d0[r] = fmaf(tv, x0, d0[r]);
            d1[r] = fmaf(tv, x1, d1[r]);
            d2[r] = fmaf(tv, x2, d2[r]);
        }
    }

    // ---------- softmax + key-mass accumulation ----------
    float ka0 = (m0 < c) ? ka[m0] : 0.f;
    float ka1 = (m1 < c) ? ka[m1] : 0.f;
    float ka2 = (m2 < c) ? ka[m2] : 0.f;
    float aW0 = 0.f, aW1 = 0.f, aW2 = 0.f;
#pragma unroll
    for (int r = 0; r < R; r++) {
        int n = n0 + r;
        if (n < c) {                       // uniform across warp
            float qan = qa[n];
            float s0 = (m0 < c) ? fmaf(SCALE, d0[r], qan + ka0) : -1e30f;
            float s1 = (m1 < c) ? fmaf(SCALE, d1[r], qan + ka1) : -1e30f;
            float s2 = (m2 < c) ? fmaf(SCALE, d2[r], qan + ka2) : -1e30f;
            float mx = fmaxf(qan, fmaxf(s0, fmaxf(s1, s2)));
#pragma unroll
            for (int o = 16; o; o >>= 1) mx = fmaxf(mx, __shfl_xor_sync(0xffffffffu, mx, o));
            float e0 = __expf(s0 - mx), e1 = __expf(s1 - mx), e2 = __expf(s2 - mx);
            float se = e0 + e1 + e2;
#pragma unroll
            for (int o = 16; o; o >>= 1) se += __shfl_xor_sync(0xffffffffu, se, o);
            se += pcount * __expf(qan - mx);
            float inv = 1.0f / se;
            aW0 = fmaf(e0, inv, aW0);
            aW1 = fmaf(e1, inv, aW1);
            aW2 = fmaf(e2, inv, aW2);
        }
    }
    if (m0 < c) atomicAdd(&sw[m0], aW0);
    if (m1 < c) atomicAdd(&sw[m1], aW1);
    if (m2 < c) atomicAdd(&sw[m2], aW2);
}

__global__ void __launch_bounds__(256) k_attn(const float* __restrict__ X) {
    int b = g_order[blockIdx.x];
    int h = blockIdx.y;
    int c = g_cnt[b];
    int st = g_start[b];
    float pcount = (float)(N_PAD - c);
    extern __shared__ float sm[];
    float* Xt   = sm;
    float* Tt   = sm + XT_F;
    float* Msub = sm + 2 * XT_F;
    float* sw   = Msub + 16 * 128;
    float* qa   = sw + 96;
    float* ka   = qa + 96;
    int tid = threadIdx.x;

    // load X transposed (zero-pad invalid columns)
    for (int idx = tid; idx < 96 * 128; idx += 256) {
        int m = idx >> 7, j = idx & 127;
        Xt[j * 97 + m] = (m < c) ? X[(st + m) * 128 + j] : 0.f;
    }
    if (tid < 96) sw[tid] = (tid < c) ? pcount * (1.0f / 96.0f) : 0.f;
    __syncthreads();

    // per-node bias terms
    if (tid < c) {
        float qacc = 0.f, kacc = 0.f;
#pragma unroll 4
        for (int i = 0; i < 128; i++) {
            float xv = Xt[i * 97 + tid];
            qacc = fmaf(xv, g_u[h][i], qacc);
            kacc = fmaf(xv, g_w2[h][i], kacc);
        }
        qa[tid] = SCALE * (qacc + g_cc[h]);
        ka[tid] = SCALE * kacc;
    }

    int rpw = (c + 7) >> 3;   // 4..12
    switch (rpw) {
        case 4:  attn_core<4 >(tid, c, h, pcount, Xt, Tt, Msub, sw, qa, ka); break;
        case 5:  attn_core<5 >(tid, c, h, pcount, Xt, Tt, Msub, sw, qa, ka); break;
        case 6:  attn_core<6 >(tid, c, h, pcount, Xt, Tt, Msub, sw, qa, ka); break;
        case 7:  attn_core<7 >(tid, c, h, pcount, Xt, Tt, Msub, sw, qa, ka); break;
        case 8:  attn_core<8 >(tid, c, h, pcount, Xt, Tt, Msub, sw, qa, ka); break;
        case 9:  attn_core<9 >(tid, c, h, pcount, Xt, Tt, Msub, sw, qa, ka); break;
        case 10: attn_core<10>(tid, c, h, pcount, Xt, Tt, Msub, sw, qa, ka); break;
        case 11: attn_core<11>(tid, c, h, pcount, Xt, Tt, Msub, sw, qa, ka); break;
        default: attn_core<12>(tid, c, h, pcount, Xt, Tt, Msub, sw, qa, ka); break;
    }
    __syncthreads();

    // z[i] = sum_m sw[m] * x_m[i]
    if (tid < 128) {
        float z = 0.f;
        for (int m = 0; m < c; m++) z = fmaf(sw[m], Xt[tid * 97 + m], z);
        g_z[(b << 10) + (h << 7) + tid] = z;
    }
}

// ================= output projection =================
__global__ void k_out(float* __restrict__ out, const float* __restrict__ bo) {
    __shared__ float zs[1024];
    int b = blockIdx.x, tid = threadIdx.x;   // 128 threads
    for (int i = tid; i < 1024; i += 128) zs[i] = g_z[b * 1024 + i];
    __syncthreads();
    float csum = bo[tid];
#pragma unroll
    for (int q = 0; q < 16; q++) csum += g_cout_part[q][tid];
    float acc = 96.0f * csum;
#pragma unroll 8
    for (int i = 0; i < 1024; i++) acc = fmaf(zs[i], g_P[i * 128 + tid], acc);
    out[b * 128 + tid] = acc;
}

// ================= launch =================
extern "C" void kernel_launch(void* const* d_in, const int* in_sizes, int n_in,
                              void* d_out, int out_size) {
    const float* x     = (const float*)d_in[0];
    const int*   batch = (const int*)  d_in[1];
    const float* Wq    = (const float*)d_in[2];
    const float* bq    = (const float*)d_in[3];
    const float* Wk    = (const float*)d_in[4];
    const float* bk    = (const float*)d_in[5];
    const float* Wv    = (const float*)d_in[6];
    const float* bv    = (const float*)d_in[7];
    const float* Wo    = (const float*)d_in[8];
    const float* bo    = (const float*)d_in[9];
    float* out = (float*)d_out;
    int total = in_sizes[1];

    cudaFuncSetAttribute(k_attn, cudaFuncAttributeMaxDynamicSharedMemorySize, SMEM_B);

    k_prep<<<522, 256>>>(batch, Wq, bq, Wk, bk, Wv, bv, Wo, bo, total);
    k_attn<<<dim3(BATCHES, HEADS), 256, SMEM_B>>>(x);
    k_out<<<BATCHES, 128>>>(out, bo);
}

// round 4
// speedup vs baseline: 2.2152x; 1.1946x over previous
#include <cuda_runtime.h>
#include <cuda_bf16.h>
#include <math.h>
#include <stdint.h>

#define BATCHES   64
#define HEADS     8
#define HIDDEN    256
#define DTOT      2048
#define N_PAD     96
#define SCALE     0.08838834764831845f   // 1/sqrt(128)

// ---------------- device scratch ----------------
__device__ int   g_cnt[BATCHES];
__device__ int   g_start[BATCHES];
__device__ int   g_order[BATCHES];
__device__ float g_M2[HEADS * 128 * 128];   // M2[h][i][j] = (Wq_h @ Wk_h^T)[i][j]
__device__ float g_P[1024 * 128];           // P[(h*128+i)*128+j] = (Wv_h @ Wo_h)[i][j]
__device__ float g_u[HEADS][128];
__device__ float g_w2[HEADS][128];
__device__ float g_cc[HEADS];
__device__ float g_cout_part[16][128];
__device__ float g_z[BATCHES * 1024];

// ================= prep kernel =================
// bid 0..127   : M2 32x32 tiles (launched first)
// bid 128..255 : P  32x32 tiles
// bid 256      : counts/starts + rank sort
// bid 257      : cc[h]
// bid 258..513 : u / w2
// bid 514..521 : cout partials
__global__ void k_prep(const int* __restrict__ batch,
                       const float* __restrict__ Wq, const float* __restrict__ bq,
                       const float* __restrict__ Wk, const float* __restrict__ bk,
                       const float* __restrict__ Wv, const float* __restrict__ bv,
                       const float* __restrict__ Wo, const float* __restrict__ bo,
                       int total) {
    int bid = blockIdx.x;
    int tid = threadIdx.x;

    if (bid < 256) {
        bool doP = (bid >= 128);
        int q = bid & 127;
        int h = q >> 4;
        int i0 = ((q >> 2) & 3) * 32, j0 = (q & 3) * 32;
        __shared__ float As[32][33];
        __shared__ float Bs[32][33];
        int tx = tid & 15, ty = tid >> 4;
        int cc_ = tid & 31, rb_ = tid >> 5;
        float a00 = 0, a01 = 0, a10 = 0, a11 = 0;
        float ra[4], rbv[4];
#pragma unroll
        for (int p = 0; p < 4; p++) {
            int r = rb_ + p * 8;
            if (!doP) {
                ra[p]  = Wq[(i0 + r) * DTOT + h * HIDDEN + cc_];
                rbv[p] = Wk[(j0 + r) * DTOT + h * HIDDEN + cc_];
            } else {
                ra[p]  = Wv[(i0 + r) * DTOT + h * HIDDEN + cc_];
                rbv[p] = Wo[(h * HIDDEN + r) * 128 + j0 + cc_];
            }
        }
        for (int ch = 0; ch < 8; ch++) {
            __syncthreads();
#pragma unroll
            for (int p = 0; p < 4; p++) {
                As[rb_ + p * 8][cc_] = ra[p];
                Bs[rb_ + p * 8][cc_] = rbv[p];
            }
            __syncthreads();
            if (ch < 7) {
                int t0 = (ch + 1) * 32;
#pragma unroll
                for (int p = 0; p < 4; p++) {
                    int r = rb_ + p * 8;
                    if (!doP) {
                        ra[p]  = Wq[(i0 + r) * DTOT + h * HIDDEN + t0 + cc_];
                        rbv[p] = Wk[(j0 + r) * DTOT + h * HIDDEN + t0 + cc_];
                    } else {
                        ra[p]  = Wv[(i0 + r) * DTOT + h * HIDDEN + t0 + cc_];
                        rbv[p] = Wo[(h * HIDDEN + t0 + r) * 128 + j0 + cc_];
                    }
                }
            }
            if (!doP) {
#pragma unroll
                for (int t = 0; t < 32; t++) {
                    float x0 = As[tx * 2][t], x1 = As[tx * 2 + 1][t];
                    float y0 = Bs[ty * 2][t], y1 = Bs[ty * 2 + 1][t];
                    a00 = fmaf(x0, y0, a00); a01 = fmaf(x0, y1, a01);
                    a10 = fmaf(x1, y0, a10); a11 = fmaf(x1, y1, a11);
                }
            } else {
#pragma unroll
                for (int t = 0; t < 32; t++) {
                    float x0 = As[tx * 2][t], x1 = As[tx * 2 + 1][t];
                    float y0 = Bs[t][ty * 2], y1 = Bs[t][ty * 2 + 1];
                    a00 = fmaf(x0, y0, a00); a01 = fmaf(x0, y1, a01);
                    a10 = fmaf(x1, y0, a10); a11 = fmaf(x1, y1, a11);
                }
            }
        }
        int i = i0 + tx * 2, j = j0 + ty * 2;
        float* dst = doP ? g_P : g_M2;
        dst[(h * 128 + i    ) * 128 + j    ] = a00;
        dst[(h * 128 + i    ) * 128 + j + 1] = a01;
        dst[(h * 128 + i + 1) * 128 + j    ] = a10;
        dst[(h * 128 + i + 1) * 128 + j + 1] = a11;
        return;
    }
    if (bid == 256) {
        __shared__ int ends[BATCHES];
        __shared__ int cnt[BATCHES];
        for (int i = tid; i < total; i += 256) {
            int bcur = batch[i];
            int bnxt = (i + 1 < total) ? batch[i + 1] : -1;
            if (bcur != bnxt) ends[bcur] = i + 1;
        }
        __syncthreads();
        if (tid < BATCHES) {
            int e = ends[tid];
            int s = (tid > 0) ? ends[tid - 1] : 0;
            g_start[tid] = s;
            cnt[tid] = e - s;
            g_cnt[tid] = e - s;
        }
        __syncthreads();
        if (tid < BATCHES) {
            int myc = cnt[tid];
            int rank = 0;
#pragma unroll 8
            for (int b = 0; b < BATCHES; b++) {
                int cb = cnt[b];
                rank += (cb > myc) || (cb == myc && b < tid);
            }
            g_order[rank] = tid;
        }
        return;
    }
    if (bid == 257) {
        int h = tid >> 5, lane = tid & 31;
        float s = 0.f;
#pragma unroll
        for (int q = 0; q < 8; q++) {
            int k = h * HIDDEN + lane + 32 * q;
            s = fmaf(bq[k], bk[k], s);
        }
#pragma unroll
        for (int o = 16; o; o >>= 1) s += __shfl_xor_sync(0xffffffffu, s, o);
        if (lane == 0) g_cc[h] = s;
        return;
    }
    if (bid < 514) {
        int gw = (bid - 258) * 8 + (tid >> 5);
        int lane = tid & 31;
        int which = gw >> 10;
        int h = (gw >> 7) & 7, i = gw & 127;
        const float* W  = which ? Wk : Wq;
        const float* bb = which ? bq : bk;
        float s = 0.f;
#pragma unroll
        for (int q = 0; q < 8; q++) {
            int k = lane + 32 * q;
            s = fmaf(W[i * DTOT + h * HIDDEN + k], bb[h * HIDDEN + k], s);
        }
#pragma unroll
        for (int o = 16; o; o >>= 1) s += __shfl_xor_sync(0xffffffffu, s, o);
        if (lane == 0) {
            if (which) g_w2[h][i] = s; else g_u[h][i] = s;
        }
        return;
    }
    {
        int p = bid - 514;
        int j = tid & 127;
        int half = tid >> 7;
        int k0 = p * 256 + half * 128;
        float s = 0.f;
#pragma unroll 8
        for (int kk = 0; kk < 128; kk++) {
            int k = k0 + kk;
            s = fmaf(bv[k], Wo[k * 128 + j], s);
        }
        g_cout_part[p * 2 + half][j] = s;
    }
}

// ================= fused attention (tf32 tensor cores) =================
#define XS 104                               // 104 % 32 == 8 -> conflict-free mma fragment LDS
#define XT_FLOATS (128 * XS)
#define SMEM_FLOATS (2 * XT_FLOATS + 4 * 96)
#define SMEM_BYTES  (SMEM_FLOATS * 4)

__device__ __forceinline__ void mma_tf32(float c[4],
    uint32_t a0, uint32_t a1, uint32_t a2, uint32_t a3,
    uint32_t b0, uint32_t b1) {
    asm volatile(
        "mma.sync.aligned.m16n8k8.row.col.f32.tf32.tf32.f32 "
        "{%0,%1,%2,%3}, {%4,%5,%6,%7}, {%8,%9}, {%0,%1,%2,%3};\n"
        : "+f"(c[0]), "+f"(c[1]), "+f"(c[2]), "+f"(c[3])
        : "r"(a0), "r"(a1), "r"(a2), "r"(a3), "r"(b0), "r"(b1));
}

template <int R>   // R = ceil(c/8), 4..12
__device__ __forceinline__ void attn_core(
    int tid, int c, int h, float pcount,
    float* __restrict__ Xt, float* __restrict__ Tt,
    float* __restrict__ sw, const float* __restrict__ qa,
    const float* __restrict__ ka, float* __restrict__ inv)
{
    const int w = tid >> 5, lane = tid & 31;
    const int la = lane & 3, lb = lane >> 2;
    const int WS = (R + 1) >> 1;             // ceil(c/16)
    const float* Mg = g_M2 + (h << 14);

    // ---------- GEMM1: Tt[j][n] = (M^T X^T)[j][n]; warp w owns rows 16w..16w+15 ----------
    {
        float c1[R][4];
#pragma unroll
        for (int r = 0; r < R; r++) { c1[r][0] = 0; c1[r][1] = 0; c1[r][2] = 0; c1[r][3] = 0; }
        uint32_t a0, a1, a2, a3;
        {
            const float* ap = Mg + la * 128 + 16 * w + lb;
            a0 = __float_as_uint(ap[0]);   a1 = __float_as_uint(ap[8]);
            a2 = __float_as_uint(ap[512]); a3 = __float_as_uint(ap[520]);
        }
#pragma unroll
        for (int ks = 0; ks < 16; ks++) {
            uint32_t na0 = 0, na1 = 0, na2 = 0, na3 = 0;
            if (ks < 15) {
                const float* ap = Mg + ((ks + 1) * 8 + la) * 128 + 16 * w + lb;
                na0 = __float_as_uint(ap[0]);   na1 = __float_as_uint(ap[8]);
                na2 = __float_as_uint(ap[512]); na3 = __float_as_uint(ap[520]);
            }
            const float* xb0 = Xt + (ks * 8 + la) * XS + lb;
            const float* xb1 = xb0 + 4 * XS;
#pragma unroll
            for (int nt = 0; nt < R; nt++) {
                uint32_t b0 = __float_as_uint(xb0[nt * 8]);
                uint32_t b1 = __float_as_uint(xb1[nt * 8]);
                mma_tf32(c1[nt], a0, a1, a2, a3, b0, b1);
            }
            if (ks < 15) { a0 = na0; a1 = na1; a2 = na2; a3 = na3; }
        }
        int r0 = 16 * w + lb;
#pragma unroll
        for (int nt = 0; nt < R; nt++) {
            *reinterpret_cast<float2*>(&Tt[r0 * XS + nt * 8 + 2 * la]) =
                make_float2(c1[nt][0], c1[nt][1]);
            *reinterpret_cast<float2*>(&Tt[(r0 + 8) * XS + nt * 8 + 2 * la]) =
                make_float2(c1[nt][2], c1[nt][3]);
        }
    }
    __syncthreads();

    // ---------- GEMM2: S[n][m] = sum_j T[n][j] X[m][j]; warps < WS ----------
    float d[R][4];
#pragma unroll
    for (int r = 0; r < R; r++) { d[r][0] = 0; d[r][1] = 0; d[r][2] = 0; d[r][3] = 0; }
    if (w < WS) {
#pragma unroll
        for (int ks = 0; ks < 16; ks++) {
            const float* tp = Tt + (ks * 8 + la) * XS + 16 * w + lb;
            uint32_t a0 = __float_as_uint(tp[0]);
            uint32_t a1 = __float_as_uint(tp[8]);
            uint32_t a2 = __float_as_uint(tp[4 * XS]);
            uint32_t a3 = __float_as_uint(tp[4 * XS + 8]);
            const float* xb0 = Xt + (ks * 8 + la) * XS + lb;
            const float* xb1 = xb0 + 4 * XS;
#pragma unroll
            for (int mt = 0; mt < R; mt++) {
                uint32_t b0 = __float_as_uint(xb0[mt * 8]);
                uint32_t b1 = __float_as_uint(xb1[mt * 8]);
                mma_tf32(d[mt], a0, a1, a2, a3, b0, b1);
            }
        }
    }
    __syncthreads();                          // all Tt reads complete before overwrite
    float* Ss = Tt;                           // reuse: Ss[m][n], stride XS
    if (w < WS) {
        int nb = 16 * w + lb;
#pragma unroll
        for (int mt = 0; mt < R; mt++) {
            int mb = mt * 8 + 2 * la;
            Ss[(mb    ) * XS + nb    ] = d[mt][0];
            Ss[(mb + 1) * XS + nb    ] = d[mt][1];
            Ss[(mb    ) * XS + nb + 8] = d[mt][2];
            Ss[(mb + 1) * XS + nb + 8] = d[mt][3];
        }
    }
    __syncthreads();

    // ---------- softmax per query n ----------
    if (tid < c) {
        int n = tid;
        float qan = qa[n];
        float mx = qan;
        for (int m = 0; m < c; m++) {
            float s = fmaf(SCALE, Ss[m * XS + n], qan + ka[m]);
            mx = fmaxf(mx, s);
        }
        float se = pcount * __expf(qan - mx);
        for (int m = 0; m < c; m++) {
            float s = fmaf(SCALE, Ss[m * XS + n], qan + ka[m]);
            float e = __expf(s - mx);
            Ss[m * XS + n] = e;
            se += e;
        }
        inv[n] = 1.0f / se;
    }
    __syncthreads();

    // ---------- column sums: sw[m] = p/96 + sum_n w[n][m]/se[n] ----------
    for (int m = w; m < c; m += 8) {
        float part = 0.f;
#pragma unroll
        for (int q = 0; q < 3; q++) {
            int n = lane + 32 * q;
            if (n < c) part = fmaf(Ss[m * XS + n], inv[n], part);
        }
#pragma unroll
        for (int o = 16; o; o >>= 1) part += __shfl_xor_sync(0xffffffffu, part, o);
        if (lane == 0) sw[m] = pcount * (1.0f / 96.0f) + part;
    }
}

__global__ void __launch_bounds__(256, 2) k_attn(const float* __restrict__ X) {
    int b = g_order[blockIdx.x];
    int h = blockIdx.y;
    int c = g_cnt[b];
    int st = g_start[b];
    float pcount = (float)(N_PAD - c);
    extern __shared__ float sm[];
    float* Xt  = sm;
    float* Tt  = sm + XT_FLOATS;
    float* sw  = sm + 2 * XT_FLOATS;
    float* qa  = sw + 96;
    float* ka  = qa + 96;
    float* inv = ka + 96;
    int tid = threadIdx.x;

    // stage X coalesced into Tt (stride 129), transpose into Xt (stride XS)
    float* stage = Tt;
    for (int idx = tid; idx < c * 128; idx += 256) {
        int m = idx >> 7, j = idx & 127;
        stage[m * 129 + j] = X[(st + m) * 128 + j];
    }
    __syncthreads();
    for (int idx = tid; idx < 128 * 96; idx += 256) {
        int j = idx / 96, m = idx - j * 96;
        Xt[j * XS + m] = (m < c) ? stage[m * 129 + j] : 0.f;
    }
    __syncthreads();

    // per-node bias terms
    if (tid < c) {
        float qacc = 0.f, kacc = 0.f;
#pragma unroll 4
        for (int i = 0; i < 128; i++) {
            float xv = Xt[i * XS + tid];
            qacc = fmaf(xv, g_u[h][i], qacc);
            kacc = fmaf(xv, g_w2[h][i], kacc);
        }
        qa[tid] = SCALE * (qacc + g_cc[h]);
        ka[tid] = SCALE * kacc;
    }

    int rpw = (c + 7) >> 3;
    switch (rpw) {
        case 4:  attn_core<4 >(tid, c, h, pcount, Xt, Tt, sw, qa, ka, inv); break;
        case 5:  attn_core<5 >(tid, c, h, pcount, Xt, Tt, sw, qa, ka, inv); break;
        case 6:  attn_core<6 >(tid, c, h, pcount, Xt, Tt, sw, qa, ka, inv); break;
        case 7:  attn_core<7 >(tid, c, h, pcount, Xt, Tt, sw, qa, ka, inv); break;
        case 8:  attn_core<8 >(tid, c, h, pcount, Xt, Tt, sw, qa, ka, inv); break;
        case 9:  attn_core<9 >(tid, c, h, pcount, Xt, Tt, sw, qa, ka, inv); break;
        case 10: attn_core<10>(tid, c, h, pcount, Xt, Tt, sw, qa, ka, inv); break;
        case 11: attn_core<11>(tid, c, h, pcount, Xt, Tt, sw, qa, ka, inv); break;
        default: attn_core<12>(tid, c, h, pcount, Xt, Tt, sw, qa, ka, inv); break;
    }
    __syncthreads();

    // z[i] = sum_m sw[m] * x_m[i]   (lane-contiguous reads + shuffle reduce)
    {
        int w = tid >> 5, lane = tid & 31;
#pragma unroll
        for (int q = 0; q < 16; q++) {
            int i = w + 8 * q;
            float part = 0.f;
#pragma unroll
            for (int q2 = 0; q2 < 3; q2++) {
                int m = lane + 32 * q2;
                if (m < c) part = fmaf(sw[m], Xt[i * XS + m], part);
            }
#pragma unroll
            for (int o = 16; o; o >>= 1) part += __shfl_xor_sync(0xffffffffu, part, o);
            if (lane == 0) g_z[(b << 10) + (h << 7) + i] = part;
        }
    }
}

// ================= output projection =================
__global__ void k_out(float* __restrict__ out, const float* __restrict__ bo) {
    __shared__ float zs[1024];
    int b = blockIdx.x, tid = threadIdx.x;   // 128 threads
    for (int i = tid; i < 1024; i += 128) zs[i] = g_z[b * 1024 + i];
    __syncthreads();
    float csum = bo[tid];
#pragma unroll
    for (int q = 0; q < 16; q++) csum += g_cout_part[q][tid];
    float acc = 96.0f * csum;
#pragma unroll 8
    for (int i = 0; i < 1024; i++) acc = fmaf(zs[i], g_P[i * 128 + tid], acc);
    out[b * 128 + tid] = acc;
}

// ================= launch =================
extern "C" void kernel_launch(void* const* d_in, const int* in_sizes, int n_in,
                              void* d_out, int out_size) {
    const float* x     = (const float*)d_in[0];
    const int*   batch = (const int*)  d_in[1];
    const float* Wq    = (const float*)d_in[2];
    const float* bq    = (const float*)d_in[3];
    const float* Wk    = (const float*)d_in[4];
    const float* bk    = (const float*)d_in[5];
    const float* Wv    = (const float*)d_in[6];
    const float* bv    = (const float*)d_in[7];
    const float* Wo    = (const float*)d_in[8];
    const float* bo    = (const float*)d_in[9];
    float* out = (float*)d_out;
    int total = in_sizes[1];

    cudaFuncSetAttribute(k_attn, cudaFuncAttributeMaxDynamicSharedMemorySize, SMEM_BYTES);

    k_prep<<<522, 256>>>(batch, Wq, bq, Wk, bk, Wv, bv, Wo, bo, total);
    k_attn<<<dim3(BATCHES, HEADS), 256, SMEM_BYTES>>>(x);
    k_out<<<BATCHES, 128>>>(out, bo);
}

// round 5
// speedup vs baseline: 3.4730x; 1.5678x over previous
#include <cuda_runtime.h>
#include <cuda_bf16.h>
#include <math.h>
#include <stdint.h>

#define BATCHES   64
#define HEADS     8
#define HIDDEN    256
#define DTOT      2048
#define N_PAD     96
#define SCALE     0.08838834764831845f   // 1/sqrt(128)

// ---------------- device scratch ----------------
__device__ int   g_cnt[BATCHES];
__device__ int   g_start[BATCHES];
__device__ int   g_order[BATCHES];
__device__ float g_M2[HEADS * 128 * 128];   // M2[h][i][j] = (Wq_h @ Wk_h^T)[i][j]
__device__ float g_P[1024 * 128];           // P[(h*128+i)*128+j] = (Wv_h @ Wo_h)[i][j]
__device__ float g_u[HEADS][128];
__device__ float g_w2[HEADS][128];
__device__ float g_cc[HEADS];
__device__ float g_cout_part[16][128];
__device__ float g_z[BATCHES * 1024];

// ================= prep kernel =================
// bid 0..127   : M2 32x32 tiles
// bid 128..255 : P  32x32 tiles
// bid 256      : counts/starts + rank sort
// bid 257      : cc[h]
// bid 258..513 : u / w2
// bid 514..521 : cout partials
__global__ void k_prep(const int* __restrict__ batch,
                       const float* __restrict__ Wq, const float* __restrict__ bq,
                       const float* __restrict__ Wk, const float* __restrict__ bk,
                       const float* __restrict__ Wv, const float* __restrict__ bv,
                       const float* __restrict__ Wo, const float* __restrict__ bo,
                       int total) {
    int bid = blockIdx.x;
    int tid = threadIdx.x;

    if (bid < 256) {
        bool doP = (bid >= 128);
        int q = bid & 127;
        int h = q >> 4;
        int i0 = ((q >> 2) & 3) * 32, j0 = (q & 3) * 32;
        // transposed layout: As[k][i], Bs[k][j]; float2 inner loads
        __shared__ __align__(16) float As[32][34];
        __shared__ __align__(16) float Bs[32][34];
        int tx = tid & 15, ty = tid >> 4;
        int cc_ = tid & 31, rb_ = tid >> 5;
        int hoff = h * HIDDEN;
        float a00 = 0, a01 = 0, a10 = 0, a11 = 0;
        float ra[4], rbv[4];
#pragma unroll
        for (int p = 0; p < 4; p++) {
            int r = rb_ + p * 8;
            if (!doP) {
                ra[p]  = Wq[(i0 + r) * DTOT + hoff + cc_];
                rbv[p] = Wk[(j0 + r) * DTOT + hoff + cc_];
            } else {
                ra[p]  = Wv[(i0 + r) * DTOT + hoff + cc_];
                rbv[p] = Wo[(hoff + r) * 128 + j0 + cc_];
            }
        }
        for (int ch = 0; ch < 8; ch++) {
            __syncthreads();
#pragma unroll
            for (int p = 0; p < 4; p++) {
                int r = rb_ + p * 8;
                As[cc_][r] = ra[p];                 // As[k][i]
                if (!doP) Bs[cc_][r] = rbv[p];      // Bs[k][j]
                else      Bs[r][cc_] = rbv[p];      // r is k-index for Wo
            }
            __syncthreads();
            if (ch < 7) {
                int t0 = (ch + 1) * 32;
#pragma unroll
                for (int p = 0; p < 4; p++) {
                    int r = rb_ + p * 8;
                    if (!doP) {
                        ra[p]  = Wq[(i0 + r) * DTOT + hoff + t0 + cc_];
                        rbv[p] = Wk[(j0 + r) * DTOT + hoff + t0 + cc_];
                    } else {
                        ra[p]  = Wv[(i0 + r) * DTOT + hoff + t0 + cc_];
                        rbv[p] = Wo[(hoff + t0 + r) * 128 + j0 + cc_];
                    }
                }
            }
#pragma unroll
            for (int t = 0; t < 32; t++) {
                float2 a2 = *reinterpret_cast<const float2*>(&As[t][tx * 2]);
                float2 b2 = *reinterpret_cast<const float2*>(&Bs[t][ty * 2]);
                a00 = fmaf(a2.x, b2.x, a00); a01 = fmaf(a2.x, b2.y, a01);
                a10 = fmaf(a2.y, b2.x, a10); a11 = fmaf(a2.y, b2.y, a11);
            }
        }
        int i = i0 + tx * 2, j = j0 + ty * 2;
        float* dst = doP ? g_P : g_M2;
        dst[(h * 128 + i    ) * 128 + j    ] = a00;
        dst[(h * 128 + i    ) * 128 + j + 1] = a01;
        dst[(h * 128 + i + 1) * 128 + j    ] = a10;
        dst[(h * 128 + i + 1) * 128 + j + 1] = a11;
        return;
    }
    if (bid == 256) {
        __shared__ int ends[BATCHES];
        __shared__ int cnt[BATCHES];
        for (int i = tid; i < total; i += 256) {
            int bcur = batch[i];
            int bnxt = (i + 1 < total) ? batch[i + 1] : -1;
            if (bcur != bnxt) ends[bcur] = i + 1;
        }
        __syncthreads();
        if (tid < BATCHES) {
            int e = ends[tid];
            int s = (tid > 0) ? ends[tid - 1] : 0;
            g_start[tid] = s;
            cnt[tid] = e - s;
            g_cnt[tid] = e - s;
        }
        __syncthreads();
        if (tid < BATCHES) {
            int myc = cnt[tid];
            int rank = 0;
#pragma unroll 8
            for (int b = 0; b < BATCHES; b++) {
                int cb = cnt[b];
                rank += (cb > myc) || (cb == myc && b < tid);
            }
            g_order[rank] = tid;
        }
        return;
    }
    if (bid == 257) {
        int h = tid >> 5, lane = tid & 31;
        float s = 0.f;
#pragma unroll
        for (int q = 0; q < 8; q++) {
            int k = h * HIDDEN + lane + 32 * q;
            s = fmaf(bq[k], bk[k], s);
        }
#pragma unroll
        for (int o = 16; o; o >>= 1) s += __shfl_xor_sync(0xffffffffu, s, o);
        if (lane == 0) g_cc[h] = s;
        return;
    }
    if (bid < 514) {
        int gw = (bid - 258) * 8 + (tid >> 5);
        int lane = tid & 31;
        int which = gw >> 10;
        int h = (gw >> 7) & 7, i = gw & 127;
        const float* W  = which ? Wk : Wq;
        const float* bb = which ? bq : bk;
        float s = 0.f;
#pragma unroll
        for (int q = 0; q < 8; q++) {
            int k = lane + 32 * q;
            s = fmaf(W[i * DTOT + h * HIDDEN + k], bb[h * HIDDEN + k], s);
        }
#pragma unroll
        for (int o = 16; o; o >>= 1) s += __shfl_xor_sync(0xffffffffu, s, o);
        if (lane == 0) {
            if (which) g_w2[h][i] = s; else g_u[h][i] = s;
        }
        return;
    }
    {
        int p = bid - 514;
        int j = tid & 127;
        int half = tid >> 7;
        int k0 = p * 256 + half * 128;
        float s = 0.f;
#pragma unroll 8
        for (int kk = 0; kk < 128; kk++) {
            int k = k0 + kk;
            s = fmaf(bv[k], Wo[k * 128 + j], s);
        }
        g_cout_part[p * 2 + half][j] = s;
    }
}

// ================= fused attention (tf32 tensor cores) =================
#define XS 104                               // 104 % 32 == 8 -> conflict-free mma fragment LDS
#define XT_FLOATS (128 * XS)
// smem: Xt + Tt/Ss + sw[96] qa[96] ka[96] us[128] ws[128]
#define SMEM_FLOATS (2 * XT_FLOATS + 3 * 96 + 256)
#define SMEM_BYTES  (SMEM_FLOATS * 4)

__device__ __forceinline__ void mma_tf32(float c[4],
    uint32_t a0, uint32_t a1, uint32_t a2, uint32_t a3,
    uint32_t b0, uint32_t b1) {
    asm volatile(
        "mma.sync.aligned.m16n8k8.row.col.f32.tf32.tf32.f32 "
        "{%0,%1,%2,%3}, {%4,%5,%6,%7}, {%8,%9}, {%0,%1,%2,%3};\n"
        : "+f"(c[0]), "+f"(c[1]), "+f"(c[2]), "+f"(c[3])
        : "r"(a0), "r"(a1), "r"(a2), "r"(a3), "r"(b0), "r"(b1));
}

template <int R>   // R = ceil(c/8), 4..12
__device__ __forceinline__ void attn_core(
    int tid, int c, int h, float pcount,
    float* __restrict__ Xt, float* __restrict__ Tt,
    float* __restrict__ sw, const float* __restrict__ qa,
    const float* __restrict__ ka)
{
    const int w = tid >> 5, lane = tid & 31;
    const int la = lane & 3, lb = lane >> 2;
    const int WS = (R + 1) >> 1;             // ceil(c/16)
    const float* Mg = g_M2 + (h << 14);

    // ---------- GEMM1: Tt[j][n] = (M^T X^T)[j][n]; warp w owns rows 16w..16w+15 ----------
    {
        float c1[R][4];
#pragma unroll
        for (int r = 0; r < R; r++) { c1[r][0] = 0; c1[r][1] = 0; c1[r][2] = 0; c1[r][3] = 0; }
        // depth-2 register prefetch of A fragments
        uint32_t a0, a1, a2, a3, n0r, n1r, n2r, n3r;
        {
            const float* ap = Mg + la * 128 + 16 * w + lb;
            a0 = __float_as_uint(ap[0]);   a1 = __float_as_uint(ap[8]);
            a2 = __float_as_uint(ap[512]); a3 = __float_as_uint(ap[520]);
            const float* ap1 = Mg + (8 + la) * 128 + 16 * w + lb;
            n0r = __float_as_uint(ap1[0]);   n1r = __float_as_uint(ap1[8]);
            n2r = __float_as_uint(ap1[512]); n3r = __float_as_uint(ap1[520]);
        }
#pragma unroll
        for (int ks = 0; ks < 16; ks++) {
            uint32_t p0 = 0, p1 = 0, p2 = 0, p3 = 0;
            if (ks < 14) {
                const float* ap = Mg + ((ks + 2) * 8 + la) * 128 + 16 * w + lb;
                p0 = __float_as_uint(ap[0]);   p1 = __float_as_uint(ap[8]);
                p2 = __float_as_uint(ap[512]); p3 = __float_as_uint(ap[520]);
            }
            const float* xb0 = Xt + (ks * 8 + la) * XS + lb;
            const float* xb1 = xb0 + 4 * XS;
#pragma unroll
            for (int nt = 0; nt < R; nt++) {
                uint32_t b0 = __float_as_uint(xb0[nt * 8]);
                uint32_t b1 = __float_as_uint(xb1[nt * 8]);
                mma_tf32(c1[nt], a0, a1, a2, a3, b0, b1);
            }
            a0 = n0r; a1 = n1r; a2 = n2r; a3 = n3r;
            n0r = p0; n1r = p1; n2r = p2; n3r = p3;
        }
        int r0 = 16 * w + lb;
#pragma unroll
        for (int nt = 0; nt < R; nt++) {
            *reinterpret_cast<float2*>(&Tt[r0 * XS + nt * 8 + 2 * la]) =
                make_float2(c1[nt][0], c1[nt][1]);
            *reinterpret_cast<float2*>(&Tt[(r0 + 8) * XS + nt * 8 + 2 * la]) =
                make_float2(c1[nt][2], c1[nt][3]);
        }
    }
    __syncthreads();

    // ---------- GEMM2: S[n][m] = sum_j T[n][j] X[m][j]; warps < WS ----------
    float d[R][4];
#pragma unroll
    for (int r = 0; r < R; r++) { d[r][0] = 0; d[r][1] = 0; d[r][2] = 0; d[r][3] = 0; }
    if (w < WS) {
#pragma unroll
        for (int ks = 0; ks < 16; ks++) {
            const float* tp = Tt + (ks * 8 + la) * XS + 16 * w + lb;
            uint32_t a0 = __float_as_uint(tp[0]);
            uint32_t a1 = __float_as_uint(tp[8]);
            uint32_t a2 = __float_as_uint(tp[4 * XS]);
            uint32_t a3 = __float_as_uint(tp[4 * XS + 8]);
            const float* xb0 = Xt + (ks * 8 + la) * XS + lb;
            const float* xb1 = xb0 + 4 * XS;
#pragma unroll
            for (int mt = 0; mt < R; mt++) {
                uint32_t b0 = __float_as_uint(xb0[mt * 8]);
                uint32_t b1 = __float_as_uint(xb1[mt * 8]);
                mma_tf32(d[mt], a0, a1, a2, a3, b0, b1);
            }
        }
    }
    __syncthreads();                          // all Tt reads complete before overwrite
    float* Ss = Tt;                           // reuse: Ss[n][m], stride XS (TRANSPOSED store)
    if (w < WS) {
        int nr = 16 * w + lb;                 // query row
#pragma unroll
        for (int mt = 0; mt < R; mt++) {
            int mb = mt * 8 + 2 * la;         // key col
            Ss[(nr    ) * XS + mb    ] = d[mt][0];
            Ss[(nr    ) * XS + mb + 1] = d[mt][1];
            Ss[(nr + 8) * XS + mb    ] = d[mt][2];
            Ss[(nr + 8) * XS + mb + 1] = d[mt][3];
        }
    }
    __syncthreads();

    // ---------- fused softmax + key-mass (warp-lane parallel, no max shift) ----------
    const int m0 = lane, m1 = lane + 32, m2 = lane + 64;
    const bool v0 = m0 < c, v1 = m1 < c, v2 = m2 < c;
    const float ka0 = v0 ? ka[m0] : 0.f;
    const float ka1 = v1 ? ka[m1] : 0.f;
    const float ka2 = v2 ? ka[m2] : 0.f;
    float aW0 = 0.f, aW1 = 0.f, aW2 = 0.f;
#pragma unroll
    for (int k = 0; k < 12; k++) {
        int n = w + 8 * k;
        if (n < c) {                           // warp-uniform
            float qan = qa[n];
            const float* Sr = Ss + n * XS;
            float e0 = v0 ? __expf(fmaf(SCALE, Sr[m0], qan + ka0)) : 0.f;
            float e1 = v1 ? __expf(fmaf(SCALE, Sr[m1], qan + ka1)) : 0.f;
            float e2 = v2 ? __expf(fmaf(SCALE, Sr[m2], qan + ka2)) : 0.f;
            float se = e0 + e1 + e2;
#pragma unroll
            for (int o = 16; o; o >>= 1) se += __shfl_xor_sync(0xffffffffu, se, o);
            se += pcount * __expf(qan);        // padded-key mass
            float iv = __fdividef(1.0f, se);
            aW0 = fmaf(e0, iv, aW0);
            aW1 = fmaf(e1, iv, aW1);
            aW2 = fmaf(e2, iv, aW2);
        }
    }
    if (v0) atomicAdd(&sw[m0], aW0);
    if (v1) atomicAdd(&sw[m1], aW1);
    if (v2) atomicAdd(&sw[m2], aW2);
}

__global__ void __launch_bounds__(256, 2) k_attn(const float* __restrict__ X) {
    int b = g_order[blockIdx.x];
    int h = blockIdx.y;
    int c = g_cnt[b];
    int st = g_start[b];
    float pcount = (float)(N_PAD - c);
    extern __shared__ float sm[];
    float* Xt = sm;
    float* Tt = sm + XT_FLOATS;
    float* sw = sm + 2 * XT_FLOATS;
    float* qa = sw + 96;
    float* ka = qa + 96;
    float* us = ka + 96;          // [128]
    float* ws = us + 128;         // [128]
    int tid = threadIdx.x;

    // stage X coalesced into Tt (stride 129), plus constants
    float* stage = Tt;
    for (int idx = tid; idx < c * 128; idx += 256) {
        int m = idx >> 7, j = idx & 127;
        stage[m * 129 + j] = X[(st + m) * 128 + j];
    }
    if (tid < 128) us[tid] = g_u[h][tid];
    else           ws[tid - 128] = g_w2[h][tid - 128];
    if (tid < 96) sw[tid] = (tid < c) ? pcount * (1.0f / 96.0f) : 0.f;
    __syncthreads();
    // transpose into Xt (stride XS), zero-pad invalid columns
    for (int idx = tid; idx < 128 * 96; idx += 256) {
        int j = idx / 96, m = idx - j * 96;
        Xt[j * XS + m] = (m < c) ? stage[m * 129 + j] : 0.f;
    }
    __syncthreads();

    // per-node bias terms (u/w2 now in smem)
    if (tid < c) {
        float ccv = g_cc[h];
        float qacc = 0.f, kacc = 0.f;
#pragma unroll 8
        for (int i = 0; i < 128; i++) {
            float xv = Xt[i * XS + tid];
            qacc = fmaf(xv, us[i], qacc);
            kacc = fmaf(xv, ws[i], kacc);
        }
        qa[tid] = SCALE * (qacc + ccv);
        ka[tid] = SCALE * kacc;
    }

    int rpw = (c + 7) >> 3;
    switch (rpw) {
        case 4:  attn_core<4 >(tid, c, h, pcount, Xt, Tt, sw, qa, ka); break;
        case 5:  attn_core<5 >(tid, c, h, pcount, Xt, Tt, sw, qa, ka); break;
        case 6:  attn_core<6 >(tid, c, h, pcount, Xt, Tt, sw, qa, ka); break;
        case 7:  attn_core<7 >(tid, c, h, pcount, Xt, Tt, sw, qa, ka); break;
        case 8:  attn_core<8 >(tid, c, h, pcount, Xt, Tt, sw, qa, ka); break;
        case 9:  attn_core<9 >(tid, c, h, pcount, Xt, Tt, sw, qa, ka); break;
        case 10: attn_core<10>(tid, c, h, pcount, Xt, Tt, sw, qa, ka); break;
        case 11: attn_core<11>(tid, c, h, pcount, Xt, Tt, sw, qa, ka); break;
        default: attn_core<12>(tid, c, h, pcount, Xt, Tt, sw, qa, ka); break;
    }
    __syncthreads();

    // z[i] = sum_m sw[m] * x_m[i]   (lane-contiguous reads + shuffle reduce)
    {
        int w = tid >> 5, lane = tid & 31;
        bool u0 = lane < c, u1 = lane + 32 < c, u2 = lane + 64 < c;
        float s0 = u0 ? sw[lane] : 0.f;
        float s1 = u1 ? sw[lane + 32] : 0.f;
        float s2 = u2 ? sw[lane + 64] : 0.f;
#pragma unroll
        for (int q = 0; q < 16; q++) {
            int i = w + 8 * q;
            const float* Xr = Xt + i * XS;
            float part = s0 * Xr[lane];
            part = fmaf(s1, u1 ? Xr[lane + 32] : 0.f, part);
            part = fmaf(s2, u2 ? Xr[lane + 64] : 0.f, part);
#pragma unroll
            for (int o = 16; o; o >>= 1) part += __shfl_xor_sync(0xffffffffu, part, o);
            if (lane == 0) g_z[(b << 10) + (h << 7) + i] = part;
        }
    }
}

// ================= output projection (1024 threads, 8-way split) =================
__global__ void k_out(float* __restrict__ out, const float* __restrict__ bo) {
    __shared__ float zs[1024];
    __shared__ float red[8][128];
    int b = blockIdx.x, tid = threadIdx.x;   // 1024 threads
    zs[tid] = g_z[b * 1024 + tid];
    __syncthreads();
    int j = tid & 127, part = tid >> 7;      // 8 parts x 128 i's
    const float* Pp = g_P + part * 128 * 128 + j;
    const float* zp = zs + part * 128;
    float acc = 0.f;
#pragma unroll 16
    for (int i = 0; i < 128; i++) acc = fmaf(zp[i], Pp[i * 128], acc);
    red[part][j] = acc;
    __syncthreads();
    if (tid < 128) {
        float csum = bo[tid];
#pragma unroll
        for (int q = 0; q < 16; q++) csum += g_cout_part[q][tid];
        float r = 96.0f * csum;
#pragma unroll
        for (int p = 0; p < 8; p++) r += red[p][tid];
        out[b * 128 + tid] = r;
    }
}

// ================= launch =================
extern "C" void kernel_launch(void* const* d_in, const int* in_sizes, int n_in,
                              void* d_out, int out_size) {
    const float* x     = (const float*)d_in[0];
    const int*   batch = (const int*)  d_in[1];
    const float* Wq    = (const float*)d_in[2];
    const float* bq    = (const float*)d_in[3];
    const float* Wk    = (const float*)d_in[4];
    const float* bk    = (const float*)d_in[5];
    const float* Wv    = (const float*)d_in[6];
    const float* bv    = (const float*)d_in[7];
    const float* Wo    = (const float*)d_in[8];
    const float* bo    = (const float*)d_in[9];
    float* out = (float*)d_out;
    int total = in_sizes[1];

    cudaFuncSetAttribute(k_attn, cudaFuncAttributeMaxDynamicSharedMemorySize, SMEM_BYTES);

    k_prep<<<522, 256>>>(batch, Wq, bq, Wk, bk, Wv, bv, Wo, bo, total);
    k_attn<<<dim3(BATCHES, HEADS), 256, SMEM_BYTES>>>(x);
    k_out<<<BATCHES, 1024>>>(out, bo);
}

// round 6
// speedup vs baseline: 4.4423x; 1.2791x over previous
#include <cuda_runtime.h>
#include <cuda_bf16.h>
#include <math.h>
#include <stdint.h>

#define BATCHES   64
#define HEADS     8
#define HIDDEN    256
#define DTOT      2048
#define N_PAD     96
#define SCALE     0.08838834764831845f   // 1/sqrt(128)

// ---------------- device scratch ----------------
__device__ int   g_cnt[BATCHES];
__device__ int   g_start[BATCHES];
__device__ int   g_order[BATCHES];
__device__ float g_M2[HEADS * 128 * 128];   // M2[h][i][j] = (Wq_h @ Wk_h^T)[i][j]
__device__ float g_P[1024 * 128];           // P[(h*128+i)*128+j] = (Wv_h @ Wo_h)[i][j]
__device__ float g_u[HEADS][128];
__device__ float g_w2[HEADS][128];
__device__ float g_cc[HEADS];
__device__ float g_cout_part[16][128];
__device__ float g_z[BATCHES * 1024];

// ================= prep kernel =================
// bid 0..31   : M2 64x64 tiles    bid 32..63 : P 64x64 tiles
// bid 64      : counts + sort     bid 65     : cc
// bid 66..321 : u / w2            bid 322..329: cout partials
#define TS 68
__global__ void k_prep(const int* __restrict__ batch,
                       const float* __restrict__ Wq, const float* __restrict__ bq,
                       const float* __restrict__ Wk, const float* __restrict__ bk,
                       const float* __restrict__ Wv, const float* __restrict__ bv,
                       const float* __restrict__ Wo, const float* __restrict__ bo,
                       int total) {
    int bid = blockIdx.x;
    int tid = threadIdx.x;

    if (bid < 64) {
        bool doP = (bid >= 32);
        int q = bid & 31;
        int h = q >> 2;
        int i0 = ((q >> 1) & 1) * 64, j0 = (q & 1) * 64;
        int hoff = h * HIDDEN;
        __shared__ __align__(16) float As[32][TS];
        __shared__ __align__(16) float Bs[32][TS];
        const float* Abase = doP ? Wv : Wq;

        // A scatter indices: f = tid*2+s : ii = f>>3, t4 = f&7
        int fA0 = tid * 2, fA1 = tid * 2 + 1;
        int iiA0 = fA0 >> 3, t4A0 = fA0 & 7;
        int iiA1 = fA1 >> 3, t4A1 = fA1 & 7;
        // B indices (M2: same pattern on Wk; P: k = f>>4, j4 = f&15 direct)
        int kB0 = fA0 >> 4, j4B0 = fA0 & 15;
        int kB1 = fA1 >> 4, j4B1 = fA1 & 15;

        float4 a0r, a1r, b0r, b1r;
        {
            a0r = *(const float4*)&Abase[(i0 + iiA0) * DTOT + hoff + t4A0 * 4];
            a1r = *(const float4*)&Abase[(i0 + iiA1) * DTOT + hoff + t4A1 * 4];
            if (!doP) {
                b0r = *(const float4*)&Wk[(j0 + iiA0) * DTOT + hoff + t4A0 * 4];
                b1r = *(const float4*)&Wk[(j0 + iiA1) * DTOT + hoff + t4A1 * 4];
            } else {
                b0r = *(const float4*)&Wo[(hoff + kB0) * 128 + j0 + j4B0 * 4];
                b1r = *(const float4*)&Wo[(hoff + kB1) * 128 + j0 + j4B1 * 4];
            }
        }
        int ty4 = (tid >> 4) * 4, tx4 = (tid & 15) * 4;
        float acc[4][4] = {};
        for (int ch = 0; ch < 8; ch++) {
            __syncthreads();
            As[t4A0 * 4 + 0][iiA0] = a0r.x; As[t4A0 * 4 + 1][iiA0] = a0r.y;
            As[t4A0 * 4 + 2][iiA0] = a0r.z; As[t4A0 * 4 + 3][iiA0] = a0r.w;
            As[t4A1 * 4 + 0][iiA1] = a1r.x; As[t4A1 * 4 + 1][iiA1] = a1r.y;
            As[t4A1 * 4 + 2][iiA1] = a1r.z; As[t4A1 * 4 + 3][iiA1] = a1r.w;
            if (!doP) {
                Bs[t4A0 * 4 + 0][iiA0] = b0r.x; Bs[t4A0 * 4 + 1][iiA0] = b0r.y;
                Bs[t4A0 * 4 + 2][iiA0] = b0r.z; Bs[t4A0 * 4 + 3][iiA0] = b0r.w;
                Bs[t4A1 * 4 + 0][iiA1] = b1r.x; Bs[t4A1 * 4 + 1][iiA1] = b1r.y;
                Bs[t4A1 * 4 + 2][iiA1] = b1r.z; Bs[t4A1 * 4 + 3][iiA1] = b1r.w;
            } else {
                *(float4*)&Bs[kB0][j4B0 * 4] = b0r;
                *(float4*)&Bs[kB1][j4B1 * 4] = b1r;
            }
            __syncthreads();
            if (ch < 7) {
                int t0 = (ch + 1) * 32;
                a0r = *(const float4*)&Abase[(i0 + iiA0) * DTOT + hoff + t0 + t4A0 * 4];
                a1r = *(const float4*)&Abase[(i0 + iiA1) * DTOT + hoff + t0 + t4A1 * 4];
                if (!doP) {
                    b0r = *(const float4*)&Wk[(j0 + iiA0) * DTOT + hoff + t0 + t4A0 * 4];
                    b1r = *(const float4*)&Wk[(j0 + iiA1) * DTOT + hoff + t0 + t4A1 * 4];
                } else {
                    b0r = *(const float4*)&Wo[(hoff + t0 + kB0) * 128 + j0 + j4B0 * 4];
                    b1r = *(const float4*)&Wo[(hoff + t0 + kB1) * 128 + j0 + j4B1 * 4];
                }
            }
#pragma unroll
            for (int t = 0; t < 32; t++) {
                float4 a4 = *(const float4*)&As[t][ty4];
                float4 b4 = *(const float4*)&Bs[t][tx4];
                float av[4] = {a4.x, a4.y, a4.z, a4.w};
                float bv4[4] = {b4.x, b4.y, b4.z, b4.w};
#pragma unroll
                for (int u = 0; u < 4; u++)
#pragma unroll
                    for (int v = 0; v < 4; v++) acc[u][v] = fmaf(av[u], bv4[v], acc[u][v]);
            }
        }
        float* dst = doP ? g_P : g_M2;
#pragma unroll
        for (int u = 0; u < 4; u++) {
            float4 val = make_float4(acc[u][0], acc[u][1], acc[u][2], acc[u][3]);
            *(float4*)&dst[(h * 128 + i0 + ty4 + u) * 128 + j0 + tx4] = val;
        }
        return;
    }
    if (bid == 64) {
        __shared__ int ends[BATCHES];
        __shared__ int cnt[BATCHES];
        for (int i = tid; i < total; i += 256) {
            int bcur = batch[i];
            int bnxt = (i + 1 < total) ? batch[i + 1] : -1;
            if (bcur != bnxt) ends[bcur] = i + 1;
        }
        __syncthreads();
        if (tid < BATCHES) {
            int e = ends[tid];
            int s = (tid > 0) ? ends[tid - 1] : 0;
            g_start[tid] = s;
            cnt[tid] = e - s;
            g_cnt[tid] = e - s;
        }
        __syncthreads();
        if (tid < BATCHES) {
            int myc = cnt[tid];
            int rank = 0;
#pragma unroll 8
            for (int b = 0; b < BATCHES; b++) {
                int cb = cnt[b];
                rank += (cb > myc) || (cb == myc && b < tid);
            }
            g_order[rank] = tid;
        }
        return;
    }
    if (bid == 65) {
        int h = tid >> 5, lane = tid & 31;
        float s = 0.f;
#pragma unroll
        for (int q = 0; q < 8; q++) {
            int k = h * HIDDEN + lane + 32 * q;
            s = fmaf(bq[k], bk[k], s);
        }
#pragma unroll
        for (int o = 16; o; o >>= 1) s += __shfl_xor_sync(0xffffffffu, s, o);
        if (lane == 0) g_cc[h] = s;
        return;
    }
    if (bid < 322) {
        int gw = (bid - 66) * 8 + (tid >> 5);
        int lane = tid & 31;
        int which = gw >> 10;
        int h = (gw >> 7) & 7, i = gw & 127;
        const float* W  = which ? Wk : Wq;
        const float* bb = which ? bq : bk;
        float s = 0.f;
#pragma unroll
        for (int q = 0; q < 8; q++) {
            int k = lane + 32 * q;
            s = fmaf(W[i * DTOT + h * HIDDEN + k], bb[h * HIDDEN + k], s);
        }
#pragma unroll
        for (int o = 16; o; o >>= 1) s += __shfl_xor_sync(0xffffffffu, s, o);
        if (lane == 0) {
            if (which) g_w2[h][i] = s; else g_u[h][i] = s;
        }
        return;
    }
    {
        int p = bid - 322;
        int j = tid & 127;
        int half = tid >> 7;
        int k0 = p * 256 + half * 128;
        float s = 0.f;
#pragma unroll 8
        for (int kk = 0; kk < 128; kk++) {
            int k = k0 + kk;
            s = fmaf(bv[k], Wo[k * 128 + j], s);
        }
        g_cout_part[p * 2 + half][j] = s;
    }
}

// dummy to shift ncu capture slot onto k_attn
__global__ void k_nop() {}

// ================= fused attention (tf32, detemplated) =================
#define XS 104                               // 104 % 32 == 8 -> conflict-free mma fragment LDS
#define XT_FLOATS (128 * XS)
#define SMEM_FLOATS (2 * XT_FLOATS + 3 * 96 + 256)
#define SMEM_BYTES  (SMEM_FLOATS * 4)

__device__ __forceinline__ void mma_tf32(float c[4],
    uint32_t a0, uint32_t a1, uint32_t a2, uint32_t a3,
    uint32_t b0, uint32_t b1) {
    asm volatile(
        "mma.sync.aligned.m16n8k8.row.col.f32.tf32.tf32.f32 "
        "{%0,%1,%2,%3}, {%4,%5,%6,%7}, {%8,%9}, {%0,%1,%2,%3};\n"
        : "+f"(c[0]), "+f"(c[1]), "+f"(c[2]), "+f"(c[3])
        : "r"(a0), "r"(a1), "r"(a2), "r"(a3), "r"(b0), "r"(b1));
}

__global__ void __launch_bounds__(256, 2) k_attn(const float* __restrict__ X) {
    int b = g_order[blockIdx.x];
    int h = blockIdx.y;
    int c = g_cnt[b];
    int st = g_start[b];
    float pcount = (float)(N_PAD - c);
    extern __shared__ float sm[];
    float* Xt = sm;
    float* Tt = sm + XT_FLOATS;           // stage / T / S
    float* sw = sm + 2 * XT_FLOATS;
    float* qa = sw + 96;
    float* ka = qa + 96;
    float* us = ka + 96;                  // [128]
    float* ws = us + 128;                 // [128]
    int tid = threadIdx.x;
    const int w = tid >> 5, lane = tid & 31;
    const int la = lane & 3, lb = lane >> 2;
    const int NT = (c + 7) >> 3;          // score tiles (4..12)
    const int WS = (c + 15) >> 4;         // GEMM2 warps (2..6)

    // ---- stage X as float4, stride 33 float4s (132 floats) ----
    float4* stage4 = (float4*)Tt;
    for (int idx = tid; idx < c * 32; idx += 256) {
        int m = idx >> 5, l = idx & 31;
        stage4[m * 33 + l] = *(const float4*)&X[(st + m) * 128 + 4 * l];
    }
    if (tid < 128) us[tid] = g_u[h][tid];
    else           ws[tid - 128] = g_w2[h][tid - 128];
    if (tid < 96) sw[tid] = (tid < c) ? pcount * (1.0f / 96.0f) : 0.f;
    __syncthreads();

    // ---- bias terms from staged rows (float4) ----
    if (tid < c) {
        const float4* xr = stage4 + tid * 33;
        const float4* u4 = (const float4*)us;
        const float4* w4 = (const float4*)ws;
        float qacc = 0.f, kacc = 0.f;
#pragma unroll 8
        for (int j4 = 0; j4 < 32; j4++) {
            float4 xv = xr[j4], uv = u4[j4], wv = w4[j4];
            qacc = fmaf(xv.x, uv.x, qacc); kacc = fmaf(xv.x, wv.x, kacc);
            qacc = fmaf(xv.y, uv.y, qacc); kacc = fmaf(xv.y, wv.y, kacc);
            qacc = fmaf(xv.z, uv.z, qacc); kacc = fmaf(xv.z, wv.z, kacc);
            qacc = fmaf(xv.w, uv.w, qacc); kacc = fmaf(xv.w, wv.w, kacc);
        }
        qa[tid] = SCALE * (qacc + g_cc[h]);
        ka[tid] = SCALE * kacc;
    }
    // ---- transpose into Xt (zero-pad m >= c) ----
    for (int idx = tid; idx < 128 * 96; idx += 256) {
        int j = idx / 96, m = idx - j * 96;
        Xt[j * XS + m] = (m < c) ? Tt[m * 132 + j] : 0.f;
    }
    __syncthreads();

    const float* Mg = g_M2 + (h << 14);

    // ---------- GEMM1: Tt[j][n] = sum_i M[i][j] * Xt[i][n] ----------
    {
        float c1[12][4];
#pragma unroll
        for (int r = 0; r < 12; r++) { c1[r][0] = 0; c1[r][1] = 0; c1[r][2] = 0; c1[r][3] = 0; }
        uint32_t a0, a1, a2, a3, n0r, n1r, n2r, n3r;
        {
            const float* ap = Mg + la * 128 + 16 * w + lb;
            a0 = __float_as_uint(ap[0]);   a1 = __float_as_uint(ap[8]);
            a2 = __float_as_uint(ap[512]); a3 = __float_as_uint(ap[520]);
            const float* ap1 = Mg + (8 + la) * 128 + 16 * w + lb;
            n0r = __float_as_uint(ap1[0]);   n1r = __float_as_uint(ap1[8]);
            n2r = __float_as_uint(ap1[512]); n3r = __float_as_uint(ap1[520]);
        }
#pragma unroll
        for (int ks = 0; ks < 16; ks++) {
            uint32_t p0 = 0, p1 = 0, p2 = 0, p3 = 0;
            if (ks < 14) {
                const float* ap = Mg + ((ks + 2) * 8 + la) * 128 + 16 * w + lb;
                p0 = __float_as_uint(ap[0]);   p1 = __float_as_uint(ap[8]);
                p2 = __float_as_uint(ap[512]); p3 = __float_as_uint(ap[520]);
            }
            const float* xb0 = Xt + (ks * 8 + la) * XS + lb;
            const float* xb1 = xb0 + 4 * XS;
#pragma unroll
            for (int nt = 0; nt < 12; nt++) {
                if (nt < NT) {
                    uint32_t b0 = __float_as_uint(xb0[nt * 8]);
                    uint32_t b1 = __float_as_uint(xb1[nt * 8]);
                    mma_tf32(c1[nt], a0, a1, a2, a3, b0, b1);
                }
            }
            a0 = n0r; a1 = n1r; a2 = n2r; a3 = n3r;
            n0r = p0; n1r = p1; n2r = p2; n3r = p3;
        }
        int r0 = 16 * w + lb;
#pragma unroll
        for (int nt = 0; nt < 12; nt++) {
            if (nt < NT) {
                *(float2*)&Tt[r0 * XS + nt * 8 + 2 * la] = make_float2(c1[nt][0], c1[nt][1]);
                *(float2*)&Tt[(r0 + 8) * XS + nt * 8 + 2 * la] = make_float2(c1[nt][2], c1[nt][3]);
            }
        }
    }
    __syncthreads();

    // ---------- GEMM2: S[n][m]; warps < WS, A-frag reused across all m-tiles ----------
    float d[12][4];
#pragma unroll
    for (int r = 0; r < 12; r++) { d[r][0] = 0; d[r][1] = 0; d[r][2] = 0; d[r][3] = 0; }
    if (w < WS) {
#pragma unroll
        for (int ks = 0; ks < 16; ks++) {
            const float* tp = Tt + (ks * 8 + la) * XS + 16 * w + lb;
            uint32_t a0 = __float_as_uint(tp[0]);
            uint32_t a1 = __float_as_uint(tp[8]);
            uint32_t a2 = __float_as_uint(tp[4 * XS]);
            uint32_t a3 = __float_as_uint(tp[4 * XS + 8]);
            const float* xb0 = Xt + (ks * 8 + la) * XS + lb;
            const float* xb1 = xb0 + 4 * XS;
#pragma unroll
            for (int mt = 0; mt < 12; mt++) {
                if (mt < NT) {
                    uint32_t b0 = __float_as_uint(xb0[mt * 8]);
                    uint32_t b1 = __float_as_uint(xb1[mt * 8]);
                    mma_tf32(d[mt], a0, a1, a2, a3, b0, b1);
                }
            }
        }
    }
    __syncthreads();                          // Tt reads complete before overwrite
    float* Ss = Tt;                           // Ss[n][m], stride XS
    if (w < WS) {
        int nr = 16 * w + lb;
#pragma unroll
        for (int mt = 0; mt < 12; mt++) {
            if (mt < NT) {
                int mb = mt * 8 + 2 * la;
                *(float2*)&Ss[(nr    ) * XS + mb] = make_float2(d[mt][0], d[mt][1]);
                *(float2*)&Ss[(nr + 8) * XS + mb] = make_float2(d[mt][2], d[mt][3]);
            }
        }
    }
    __syncthreads();

    // ---------- fused softmax + key-mass (no max shift; scores are O(1)) ----------
    const int m0 = lane, m1 = lane + 32, m2 = lane + 64;
    const bool v0 = m0 < c, v1 = m1 < c, v2 = m2 < c;
    const float ka0 = v0 ? ka[m0] : 0.f;
    const float ka1 = v1 ? ka[m1] : 0.f;
    const float ka2 = v2 ? ka[m2] : 0.f;
    float aW0 = 0.f, aW1 = 0.f, aW2 = 0.f;
#pragma unroll
    for (int k = 0; k < 12; k++) {
        int n = w + 8 * k;
        if (n < c) {                           // warp-uniform
            float qan = qa[n];
            const float* Sr = Ss + n * XS;
            float e0 = v0 ? __expf(fmaf(SCALE, Sr[m0], qan + ka0)) : 0.f;
            float e1 = v1 ? __expf(fmaf(SCALE, Sr[m1], qan + ka1)) : 0.f;
            float e2 = v2 ? __expf(fmaf(SCALE, Sr[m2], qan + ka2)) : 0.f;
            float se = e0 + e1 + e2;
#pragma unroll
            for (int o = 16; o; o >>= 1) se += __shfl_xor_sync(0xffffffffu, se, o);
            se += pcount * __expf(qan);
            float iv = __fdividef(1.0f, se);
            aW0 = fmaf(e0, iv, aW0);
            aW1 = fmaf(e1, iv, aW1);
            aW2 = fmaf(e2, iv, aW2);
        }
    }
    if (v0) atomicAdd(&sw[m0], aW0);
    if (v1) atomicAdd(&sw[m1], aW1);
    if (v2) atomicAdd(&sw[m2], aW2);
    __syncthreads();

    // ---------- z[i] = sum_m sw[m] * x_m[i] ----------
    {
        bool u1 = lane + 32 < c, u2 = lane + 64 < c;
        float s0 = (lane < c) ? sw[lane] : 0.f;
        float s1 = u1 ? sw[lane + 32] : 0.f;
        float s2 = u2 ? sw[lane + 64] : 0.f;
#pragma unroll
        for (int q = 0; q < 16; q++) {
            int i = w + 8 * q;
            const float* Xr = Xt + i * XS;
            float part = s0 * Xr[lane];
            part = fmaf(s1, u1 ? Xr[lane + 32] : 0.f, part);
            part = fmaf(s2, u2 ? Xr[lane + 64] : 0.f, part);
#pragma unroll
            for (int o = 16; o; o >>= 1) part += __shfl_xor_sync(0xffffffffu, part, o);
            if (lane == 0) g_z[(b << 10) + (h << 7) + i] = part;
        }
    }
}

// ================= output projection =================
__global__ void k_out(float* __restrict__ out, const float* __restrict__ bo) {
    __shared__ float zs[1024];
    __shared__ float red[8][128];
    int b = blockIdx.x, tid = threadIdx.x;   // 1024 threads
    zs[tid] = g_z[b * 1024 + tid];
    __syncthreads();
    int j = tid & 127, part = tid >> 7;
    const float* Pp = g_P + part * 128 * 128 + j;
    const float* zp = zs + part * 128;
    float acc = 0.f;
#pragma unroll 16
    for (int i = 0; i < 128; i++) acc = fmaf(zp[i], Pp[i * 128], acc);
    red[part][j] = acc;
    __syncthreads();
    if (tid < 128) {
        float csum = bo[tid];
#pragma unroll
        for (int q = 0; q < 16; q++) csum += g_cout_part[q][tid];
        float r = 96.0f * csum;
#pragma unroll
        for (int p = 0; p < 8; p++) r += red[p][tid];
        out[b * 128 + tid] = r;
    }
}

// ================= launch =================
extern "C" void kernel_launch(void* const* d_in, const int* in_sizes, int n_in,
                              void* d_out, int out_size) {
    const float* x     = (const float*)d_in[0];
    const int*   batch = (const int*)  d_in[1];
    const float* Wq    = (const float*)d_in[2];
    const float* bq    = (const float*)d_in[3];
    const float* Wk    = (const float*)d_in[4];
    const float* bk    = (const float*)d_in[5];
    const float* Wv    = (const float*)d_in[6];
    const float* bv    = (const float*)d_in[7];
    const float* Wo    = (const float*)d_in[8];
    const float* bo    = (const float*)d_in[9];
    float* out = (float*)d_out;
    int total = in_sizes[1];

    cudaFuncSetAttribute(k_attn, cudaFuncAttributeMaxDynamicSharedMemorySize, SMEM_BYTES);

    k_prep<<<330, 256>>>(batch, Wq, bq, Wk, bk, Wv, bv, Wo, bo, total);
    k_nop<<<1, 32>>>();
    k_attn<<<dim3(BATCHES, HEADS), 256, SMEM_BYTES>>>(x);
    k_out<<<BATCHES, 1024>>>(out, bo);
}

// round 7
// speedup vs baseline: 4.7377x; 1.0665x over previous
#include <cuda_runtime.h>
#include <cuda_bf16.h>
#include <math.h>
#include <stdint.h>

#define BATCHES   64
#define HEADS     8
#define HIDDEN    256
#define DTOT      2048
#define N_PAD     96
#define SCALE     0.08838834764831845f   // 1/sqrt(128)

// ---------------- device scratch ----------------
__device__ int   g_cnt[BATCHES];
__device__ int   g_start[BATCHES];
__device__ int   g_order[BATCHES];
__device__ float g_M2[HEADS * 128 * 128];   // M2[h][i][j] = (Wq_h @ Wk_h^T)[i][j]
__device__ float g_P[1024 * 128];           // P[(h*128+i)*128+j] = (Wv_h @ Wo_h)[i][j]
__device__ float g_u[HEADS][128];
__device__ float g_w2[HEADS][128];
__device__ float g_cc[HEADS];
__device__ float g_cout_part[16][128];

// ================= prep kernel =================
// bid 0..31   : M2 64x64 tiles    bid 32..63 : P 64x64 tiles
// bid 64      : counts + sort     bid 65     : cc
// bid 66..321 : u / w2            bid 322..329: cout partials
#define TS 68
__global__ void k_prep(const int* __restrict__ batch,
                       const float* __restrict__ Wq, const float* __restrict__ bq,
                       const float* __restrict__ Wk, const float* __restrict__ bk,
                       const float* __restrict__ Wv, const float* __restrict__ bv,
                       const float* __restrict__ Wo, const float* __restrict__ bo,
                       int total) {
    int bid = blockIdx.x;
    int tid = threadIdx.x;

    if (bid < 64) {
        bool doP = (bid >= 32);
        int q = bid & 31;
        int h = q >> 2;
        int i0 = ((q >> 1) & 1) * 64, j0 = (q & 1) * 64;
        int hoff = h * HIDDEN;
        __shared__ __align__(16) float As[32][TS];
        __shared__ __align__(16) float Bs[32][TS];
        const float* Abase = doP ? Wv : Wq;

        int fA0 = tid * 2, fA1 = tid * 2 + 1;
        int iiA0 = fA0 >> 3, t4A0 = fA0 & 7;
        int iiA1 = fA1 >> 3, t4A1 = fA1 & 7;
        int kB0 = fA0 >> 4, j4B0 = fA0 & 15;
        int kB1 = fA1 >> 4, j4B1 = fA1 & 15;

        float4 a0r, a1r, b0r, b1r;
        {
            a0r = *(const float4*)&Abase[(i0 + iiA0) * DTOT + hoff + t4A0 * 4];
            a1r = *(const float4*)&Abase[(i0 + iiA1) * DTOT + hoff + t4A1 * 4];
            if (!doP) {
                b0r = *(const float4*)&Wk[(j0 + iiA0) * DTOT + hoff + t4A0 * 4];
                b1r = *(const float4*)&Wk[(j0 + iiA1) * DTOT + hoff + t4A1 * 4];
            } else {
                b0r = *(const float4*)&Wo[(hoff + kB0) * 128 + j0 + j4B0 * 4];
                b1r = *(const float4*)&Wo[(hoff + kB1) * 128 + j0 + j4B1 * 4];
            }
        }
        int ty4 = (tid >> 4) * 4, tx4 = (tid & 15) * 4;
        float acc[4][4] = {};
        for (int ch = 0; ch < 8; ch++) {
            __syncthreads();
            As[t4A0 * 4 + 0][iiA0] = a0r.x; As[t4A0 * 4 + 1][iiA0] = a0r.y;
            As[t4A0 * 4 + 2][iiA0] = a0r.z; As[t4A0 * 4 + 3][iiA0] = a0r.w;
            As[t4A1 * 4 + 0][iiA1] = a1r.x; As[t4A1 * 4 + 1][iiA1] = a1r.y;
            As[t4A1 * 4 + 2][iiA1] = a1r.z; As[t4A1 * 4 + 3][iiA1] = a1r.w;
            if (!doP) {
                Bs[t4A0 * 4 + 0][iiA0] = b0r.x; Bs[t4A0 * 4 + 1][iiA0] = b0r.y;
                Bs[t4A0 * 4 + 2][iiA0] = b0r.z; Bs[t4A0 * 4 + 3][iiA0] = b0r.w;
                Bs[t4A1 * 4 + 0][iiA1] = b1r.x; Bs[t4A1 * 4 + 1][iiA1] = b1r.y;
                Bs[t4A1 * 4 + 2][iiA1] = b1r.z; Bs[t4A1 * 4 + 3][iiA1] = b1r.w;
            } else {
                *(float4*)&Bs[kB0][j4B0 * 4] = b0r;
                *(float4*)&Bs[kB1][j4B1 * 4] = b1r;
            }
            __syncthreads();
            if (ch < 7) {
                int t0 = (ch + 1) * 32;
                a0r = *(const float4*)&Abase[(i0 + iiA0) * DTOT + hoff + t0 + t4A0 * 4];
                a1r = *(const float4*)&Abase[(i0 + iiA1) * DTOT + hoff + t0 + t4A1 * 4];
                if (!doP) {
                    b0r = *(const float4*)&Wk[(j0 + iiA0) * DTOT + hoff + t0 + t4A0 * 4];
                    b1r = *(const float4*)&Wk[(j0 + iiA1) * DTOT + hoff + t0 + t4A1 * 4];
                } else {
                    b0r = *(const float4*)&Wo[(hoff + t0 + kB0) * 128 + j0 + j4B0 * 4];
                    b1r = *(const float4*)&Wo[(hoff + t0 + kB1) * 128 + j0 + j4B1 * 4];
                }
            }
#pragma unroll
            for (int t = 0; t < 32; t++) {
                float4 a4 = *(const float4*)&As[t][ty4];
                float4 b4 = *(const float4*)&Bs[t][tx4];
                float av[4] = {a4.x, a4.y, a4.z, a4.w};
                float bv4[4] = {b4.x, b4.y, b4.z, b4.w};
#pragma unroll
                for (int u = 0; u < 4; u++)
#pragma unroll
                    for (int v = 0; v < 4; v++) acc[u][v] = fmaf(av[u], bv4[v], acc[u][v]);
            }
        }
        float* dst = doP ? g_P : g_M2;
#pragma unroll
        for (int u = 0; u < 4; u++) {
            float4 val = make_float4(acc[u][0], acc[u][1], acc[u][2], acc[u][3]);
            *(float4*)&dst[(h * 128 + i0 + ty4 + u) * 128 + j0 + tx4] = val;
        }
        return;
    }
    if (bid == 64) {
        __shared__ int ends[BATCHES];
        __shared__ int cnt[BATCHES];
        for (int i = tid; i < total; i += 256) {
            int bcur = batch[i];
            int bnxt = (i + 1 < total) ? batch[i + 1] : -1;
            if (bcur != bnxt) ends[bcur] = i + 1;
        }
        __syncthreads();
        if (tid < BATCHES) {
            int e = ends[tid];
            int s = (tid > 0) ? ends[tid - 1] : 0;
            g_start[tid] = s;
            cnt[tid] = e - s;
            g_cnt[tid] = e - s;
        }
        __syncthreads();
        if (tid < BATCHES) {
            int myc = cnt[tid];
            int rank = 0;
#pragma unroll 8
            for (int b = 0; b < BATCHES; b++) {
                int cb = cnt[b];
                rank += (cb > myc) || (cb == myc && b < tid);
            }
            g_order[rank] = tid;
        }
        return;
    }
    if (bid == 65) {
        int h = tid >> 5, lane = tid & 31;
        float s = 0.f;
#pragma unroll
        for (int q = 0; q < 8; q++) {
            int k = h * HIDDEN + lane + 32 * q;
            s = fmaf(bq[k], bk[k], s);
        }
#pragma unroll
        for (int o = 16; o; o >>= 1) s += __shfl_xor_sync(0xffffffffu, s, o);
        if (lane == 0) g_cc[h] = s;
        return;
    }
    if (bid < 322) {
        int gw = (bid - 66) * 8 + (tid >> 5);
        int lane = tid & 31;
        int which = gw >> 10;
        int h = (gw >> 7) & 7, i = gw & 127;
        const float* W  = which ? Wk : Wq;
        const float* bb = which ? bq : bk;
        float s = 0.f;
#pragma unroll
        for (int q = 0; q < 8; q++) {
            int k = lane + 32 * q;
            s = fmaf(W[i * DTOT + h * HIDDEN + k], bb[h * HIDDEN + k], s);
        }
#pragma unroll
        for (int o = 16; o; o >>= 1) s += __shfl_xor_sync(0xffffffffu, s, o);
        if (lane == 0) {
            if (which) g_w2[h][i] = s; else g_u[h][i] = s;
        }
        return;
    }
    {
        int p = bid - 322;
        int j = tid & 127;
        int half = tid >> 7;
        int k0 = p * 256 + half * 128;
        float s = 0.f;
#pragma unroll 8
        for (int kk = 0; kk < 128; kk++) {
            int k = k0 + kk;
            s = fmaf(bv[k], Wo[k * 128 + j], s);
        }
        g_cout_part[p * 2 + half][j] = s;
    }
}

// ---- out init: out[b][j] = 96*(bv@Wo + bo)[j] ----
__global__ void k_init(float* __restrict__ out, const float* __restrict__ bo) {
    int b = blockIdx.x, j = threadIdx.x;
    float s = bo[j];
#pragma unroll
    for (int q = 0; q < 16; q++) s += g_cout_part[q][j];
    out[b * 128 + j] = 96.0f * s;
}

// dummy to align ncu capture slot (index 3) onto k_attn
__global__ void k_nop() {}

// ================= fused attention (tf32, 2 heads/block, fused output) =================
#define XS 104                               // 104 % 32 == 8 -> conflict-free mma fragment LDS
#define XT_FLOATS (128 * XS)
// Xt + Tt + sw[96] + qa[2][96] + ka[2][96] + u[2][128] + w[2][128] + zb[2][128]
#define SMEM_FLOATS (2 * XT_FLOATS + 96 + 2*96 + 2*96 + 2*128 + 2*128 + 2*128)
#define SMEM_BYTES  (SMEM_FLOATS * 4)

__device__ __forceinline__ void mma_tf32(float c[4],
    uint32_t a0, uint32_t a1, uint32_t a2, uint32_t a3,
    uint32_t b0, uint32_t b1) {
    asm volatile(
        "mma.sync.aligned.m16n8k8.row.col.f32.tf32.tf32.f32 "
        "{%0,%1,%2,%3}, {%4,%5,%6,%7}, {%8,%9}, {%0,%1,%2,%3};\n"
        : "+f"(c[0]), "+f"(c[1]), "+f"(c[2]), "+f"(c[3])
        : "r"(a0), "r"(a1), "r"(a2), "r"(a3), "r"(b0), "r"(b1));
}

__global__ void __launch_bounds__(256, 2) k_attn(const float* __restrict__ X,
                                                 float* __restrict__ out) {
    int b = g_order[blockIdx.x];
    int h0 = blockIdx.y * 2;               // this block: heads h0, h0+1
    int c = g_cnt[b];
    int st = g_start[b];
    float pcount = (float)(N_PAD - c);
    extern __shared__ float sm[];
    float* Xt = sm;
    float* Tt = sm + XT_FLOATS;            // stage / T / S
    float* sw = sm + 2 * XT_FLOATS;        // [96]
    float* qa = sw + 96;                   // [2][96]
    float* ka = qa + 192;                  // [2][96]
    float* us = ka + 192;                  // [2][128]
    float* ws = us + 256;                  // [2][128]
    float* zb = ws + 256;                  // [2][128]
    int tid = threadIdx.x;
    const int w = tid >> 5, lane = tid & 31;
    const int la = lane & 3, lb = lane >> 2;
    const int NT = (c + 7) >> 3;           // score tiles (4..12)
    const int WS = (c + 15) >> 4;          // GEMM2 warps (2..6)

    // ---- stage X as float4 (stride 33 float4s = 132 floats), load head constants ----
    float4* stage4 = (float4*)Tt;
    for (int idx = tid; idx < c * 32; idx += 256) {
        int m = idx >> 5, l = idx & 31;
        stage4[m * 33 + l] = *(const float4*)&X[(st + m) * 128 + 4 * l];
    }
    if (tid < 128) { us[tid] = g_u[h0][tid];        ws[tid] = g_w2[h0][tid]; }
    else { us[tid] = g_u[h0 + 1][tid - 128];        ws[tid] = g_w2[h0 + 1][tid - 128]; }
    __syncthreads();

    // ---- bias terms for BOTH heads from staged rows ----
    if (tid < c) {
        const float4* xr = stage4 + tid * 33;
        const float4* u0 = (const float4*)us;
        const float4* u1 = (const float4*)(us + 128);
        const float4* w0 = (const float4*)ws;
        const float4* w1 = (const float4*)(ws + 128);
        float q0 = 0.f, k0 = 0.f, q1 = 0.f, k1 = 0.f;
#pragma unroll 4
        for (int j4 = 0; j4 < 32; j4++) {
            float4 xv = xr[j4];
            float4 a = u0[j4], bb = w0[j4], cc = u1[j4], dd = w1[j4];
            q0 = fmaf(xv.x, a.x, q0); k0 = fmaf(xv.x, bb.x, k0);
            q1 = fmaf(xv.x, cc.x, q1); k1 = fmaf(xv.x, dd.x, k1);
            q0 = fmaf(xv.y, a.y, q0); k0 = fmaf(xv.y, bb.y, k0);
            q1 = fmaf(xv.y, cc.y, q1); k1 = fmaf(xv.y, dd.y, k1);
            q0 = fmaf(xv.z, a.z, q0); k0 = fmaf(xv.z, bb.z, k0);
            q1 = fmaf(xv.z, cc.z, q1); k1 = fmaf(xv.z, dd.z, k1);
            q0 = fmaf(xv.w, a.w, q0); k0 = fmaf(xv.w, bb.w, k0);
            q1 = fmaf(xv.w, cc.w, q1); k1 = fmaf(xv.w, dd.w, k1);
        }
        qa[tid]       = SCALE * (q0 + g_cc[h0]);
        ka[tid]       = SCALE * k0;
        qa[96 + tid]  = SCALE * (q1 + g_cc[h0 + 1]);
        ka[96 + tid]  = SCALE * k1;
    }
    // ---- transpose stage -> Xt (zero-pad m >= c) ----
    for (int idx = tid; idx < 128 * 96; idx += 256) {
        int j = idx / 96, m = idx - j * 96;
        Xt[j * XS + m] = (m < c) ? Tt[m * 132 + j] : 0.f;
    }
    __syncthreads();

    for (int hh = 0; hh < 2; hh++) {
        const float* Mg = g_M2 + ((h0 + hh) << 14);
        const float* qah = qa + hh * 96;
        const float* kah = ka + hh * 96;

        // ---------- GEMM1: Tt[j][n] = sum_i M[i][j] * Xt[i][n] ----------
        {
            float c1[12][4];
#pragma unroll
            for (int r = 0; r < 12; r++) { c1[r][0] = 0; c1[r][1] = 0; c1[r][2] = 0; c1[r][3] = 0; }
            uint32_t a0, a1, a2, a3, n0r, n1r, n2r, n3r;
            {
                const float* ap = Mg + la * 128 + 16 * w + lb;
                a0 = __float_as_uint(ap[0]);   a1 = __float_as_uint(ap[8]);
                a2 = __float_as_uint(ap[512]); a3 = __float_as_uint(ap[520]);
                const float* ap1 = Mg + (8 + la) * 128 + 16 * w + lb;
                n0r = __float_as_uint(ap1[0]);   n1r = __float_as_uint(ap1[8]);
                n2r = __float_as_uint(ap1[512]); n3r = __float_as_uint(ap1[520]);
            }
#pragma unroll
            for (int ks = 0; ks < 16; ks++) {
                uint32_t p0 = 0, p1 = 0, p2 = 0, p3 = 0;
                if (ks < 14) {
                    const float* ap = Mg + ((ks + 2) * 8 + la) * 128 + 16 * w + lb;
                    p0 = __float_as_uint(ap[0]);   p1 = __float_as_uint(ap[8]);
                    p2 = __float_as_uint(ap[512]); p3 = __float_as_uint(ap[520]);
                }
                const float* xb0 = Xt + (ks * 8 + la) * XS + lb;
                const float* xb1 = xb0 + 4 * XS;
#pragma unroll
                for (int nt = 0; nt < 12; nt++) {
                    if (nt < NT) {
                        uint32_t b0 = __float_as_uint(xb0[nt * 8]);
                        uint32_t b1 = __float_as_uint(xb1[nt * 8]);
                        mma_tf32(c1[nt], a0, a1, a2, a3, b0, b1);
                    }
                }
                a0 = n0r; a1 = n1r; a2 = n2r; a3 = n3r;
                n0r = p0; n1r = p1; n2r = p2; n3r = p3;
            }
            __syncthreads();     // head 1: ensure softmax/z of head 0 done reading Tt
            int r0 = 16 * w + lb;
#pragma unroll
            for (int nt = 0; nt < 12; nt++) {
                if (nt < NT) {
                    *(float2*)&Tt[r0 * XS + nt * 8 + 2 * la] = make_float2(c1[nt][0], c1[nt][1]);
                    *(float2*)&Tt[(r0 + 8) * XS + nt * 8 + 2 * la] = make_float2(c1[nt][2], c1[nt][3]);
                }
            }
        }
        __syncthreads();

        // ---------- GEMM2: S[n][m]; warps < WS ----------
        float d[12][4];
#pragma unroll
        for (int r = 0; r < 12; r++) { d[r][0] = 0; d[r][1] = 0; d[r][2] = 0; d[r][3] = 0; }
        if (w < WS) {
#pragma unroll
            for (int ks = 0; ks < 16; ks++) {
                const float* tp = Tt + (ks * 8 + la) * XS + 16 * w + lb;
                uint32_t a0 = __float_as_uint(tp[0]);
                uint32_t a1 = __float_as_uint(tp[8]);
                uint32_t a2 = __float_as_uint(tp[4 * XS]);
                uint32_t a3 = __float_as_uint(tp[4 * XS + 8]);
                const float* xb0 = Xt + (ks * 8 + la) * XS + lb;
                const float* xb1 = xb0 + 4 * XS;
#pragma unroll
                for (int mt = 0; mt < 12; mt++) {
                    if (mt < NT) {
                        uint32_t b0 = __float_as_uint(xb0[mt * 8]);
                        uint32_t b1 = __float_as_uint(xb1[mt * 8]);
                        mma_tf32(d[mt], a0, a1, a2, a3, b0, b1);
                    }
                }
            }
        }
        __syncthreads();                      // Tt reads done before overwrite
        float* Ss = Tt;                       // Ss[n][m], stride XS
        if (w < WS) {
            int nr = 16 * w + lb;
#pragma unroll
            for (int mt = 0; mt < 12; mt++) {
                if (mt < NT) {
                    int mb = mt * 8 + 2 * la;
                    *(float2*)&Ss[(nr    ) * XS + mb] = make_float2(d[mt][0], d[mt][1]);
                    *(float2*)&Ss[(nr + 8) * XS + mb] = make_float2(d[mt][2], d[mt][3]);
                }
            }
        }
        if (tid < 96) sw[tid] = (tid < c) ? pcount * (1.0f / 96.0f) : 0.f;
        __syncthreads();

        // ---------- fused softmax + key-mass (no max shift; scores O(1)) ----------
        const int m0 = lane, m1 = lane + 32, m2 = lane + 64;
        const bool v0 = m0 < c, v1 = m1 < c, v2 = m2 < c;
        const float ka0 = v0 ? kah[m0] : 0.f;
        const float ka1 = v1 ? kah[m1] : 0.f;
        const float ka2 = v2 ? kah[m2] : 0.f;
        float aW0 = 0.f, aW1 = 0.f, aW2 = 0.f;
#pragma unroll
        for (int k = 0; k < 12; k++) {
            int n = w + 8 * k;
            if (n < c) {                       // warp-uniform
                float qan = qah[n];
                const float* Sr = Ss + n * XS;
                float e0 = v0 ? __expf(fmaf(SCALE, Sr[m0], qan + ka0)) : 0.f;
                float e1 = v1 ? __expf(fmaf(SCALE, Sr[m1], qan + ka1)) : 0.f;
                float e2 = v2 ? __expf(fmaf(SCALE, Sr[m2], qan + ka2)) : 0.f;
                float se = e0 + e1 + e2;
#pragma unroll
                for (int o = 16; o; o >>= 1) se += __shfl_xor_sync(0xffffffffu, se, o);
                se += pcount * __expf(qan);
                float iv = __fdividef(1.0f, se);
                aW0 = fmaf(e0, iv, aW0);
                aW1 = fmaf(e1, iv, aW1);
                aW2 = fmaf(e2, iv, aW2);
            }
        }
        if (v0) atomicAdd(&sw[m0], aW0);
        if (v1) atomicAdd(&sw[m1], aW1);
        if (v2) atomicAdd(&sw[m2], aW2);
        __syncthreads();

        // ---------- z[i] = sum_m sw[m] * x_m[i] -> zb[hh] ----------
        {
            bool u1v = lane + 32 < c, u2v = lane + 64 < c;
            float s0 = (lane < c) ? sw[lane] : 0.f;
            float s1 = u1v ? sw[lane + 32] : 0.f;
            float s2 = u2v ? sw[lane + 64] : 0.f;
#pragma unroll
            for (int q = 0; q < 16; q++) {
                int i = w + 8 * q;
                const float* Xr = Xt + i * XS;
                float part = s0 * Xr[lane];
                part = fmaf(s1, u1v ? Xr[lane + 32] : 0.f, part);
                part = fmaf(s2, u2v ? Xr[lane + 64] : 0.f, part);
#pragma unroll
                for (int o = 16; o; o >>= 1) part += __shfl_xor_sync(0xffffffffu, part, o);
                if (lane == 0) zb[hh * 128 + i] = part;
            }
        }
        __syncthreads();
    }

    // ---------- fused output: out[b][j] += sum_i zb[half][i] * P[h0+half][i][j] ----------
    {
        int half = tid >> 7, j = tid & 127;
        const float* Pp = g_P + ((h0 + half) << 14) + j;
        const float* zp = zb + half * 128;
        float a0 = 0.f, a1 = 0.f, a2 = 0.f, a3 = 0.f;
#pragma unroll
        for (int i = 0; i < 128; i += 4) {
            a0 = fmaf(zp[i    ], Pp[(i    ) * 128], a0);
            a1 = fmaf(zp[i + 1], Pp[(i + 1) * 128], a1);
            a2 = fmaf(zp[i + 2], Pp[(i + 2) * 128], a2);
            a3 = fmaf(zp[i + 3], Pp[(i + 3) * 128], a3);
        }
        atomicAdd(&out[b * 128 + j], (a0 + a1) + (a2 + a3));
    }
}

// ================= launch =================
extern "C" void kernel_launch(void* const* d_in, const int* in_sizes, int n_in,
                              void* d_out, int out_size) {
    const float* x     = (const float*)d_in[0];
    const int*   batch = (const int*)  d_in[1];
    const float* Wq    = (const float*)d_in[2];
    const float* bq    = (const float*)d_in[3];
    const float* Wk    = (const float*)d_in[4];
    const float* bk    = (const float*)d_in[5];
    const float* Wv    = (const float*)d_in[6];
    const float* bv    = (const float*)d_in[7];
    const float* Wo    = (const float*)d_in[8];
    const float* bo    = (const float*)d_in[9];
    float* out = (float*)d_out;
    int total = in_sizes[1];

    cudaFuncSetAttribute(k_attn, cudaFuncAttributeMaxDynamicSharedMemorySize, SMEM_BYTES);

    k_prep<<<330, 256>>>(batch, Wq, bq, Wk, bk, Wv, bv, Wo, bo, total);
    k_init<<<BATCHES, 128>>>(out, bo);
    k_nop<<<1, 32>>>();
    k_attn<<<dim3(BATCHES, 4), 256, SMEM_BYTES>>>(x, out);
}

// round 14
// speedup vs baseline: 4.8331x; 1.0201x over previous
#include <cuda_runtime.h>
#include <cuda_bf16.h>
#include <math.h>
#include <stdint.h>

#define BATCHES   64
#define HEADS     8
#define HIDDEN    256
#define DTOT      2048
#define N_PAD     96
#define SCALE     0.08838834764831845f   // 1/sqrt(128)

// ---------------- device scratch ----------------
__device__ int   g_cnt[BATCHES];
__device__ int   g_start[BATCHES];
__device__ int   g_order[BATCHES];
__device__ float g_M2[HEADS * 128 * 128];   // M2[h][i][j] = (Wq_h @ Wk_h^T)[i][j]
__device__ float g_P[1024 * 128];           // P[(h*128+i)*128+j] = (Wv_h @ Wo_h)[i][j]
__device__ float g_u[HEADS][128];
__device__ float g_w2[HEADS][128];
__device__ float g_cc[HEADS];
__device__ float g_cout_part[16][128];

// ================= prep kernel (identical to R7) =================
#define TS 68
__global__ void k_prep(const int* __restrict__ batch,
                       const float* __restrict__ Wq, const float* __restrict__ bq,
                       const float* __restrict__ Wk, const float* __restrict__ bk,
                       const float* __restrict__ Wv, const float* __restrict__ bv,
                       const float* __restrict__ Wo, const float* __restrict__ bo,
                       int total) {
    int bid = blockIdx.x;
    int tid = threadIdx.x;

    if (bid < 64) {
        bool doP = (bid >= 32);
        int q = bid & 31;
        int h = q >> 2;
        int i0 = ((q >> 1) & 1) * 64, j0 = (q & 1) * 64;
        int hoff = h * HIDDEN;
        __shared__ __align__(16) float As[32][TS];
        __shared__ __align__(16) float Bs[32][TS];
        const float* Abase = doP ? Wv : Wq;

        int fA0 = tid * 2, fA1 = tid * 2 + 1;
        int iiA0 = fA0 >> 3, t4A0 = fA0 & 7;
        int iiA1 = fA1 >> 3, t4A1 = fA1 & 7;
        int kB0 = fA0 >> 4, j4B0 = fA0 & 15;
        int kB1 = fA1 >> 4, j4B1 = fA1 & 15;

        float4 a0r, a1r, b0r, b1r;
        a0r = *(const float4*)&Abase[(i0 + iiA0) * DTOT + hoff + t4A0 * 4];
        a1r = *(const float4*)&Abase[(i0 + iiA1) * DTOT + hoff + t4A1 * 4];
        if (!doP) {
            b0r = *(const float4*)&Wk[(j0 + iiA0) * DTOT + hoff + t4A0 * 4];
            b1r = *(const float4*)&Wk[(j0 + iiA1) * DTOT + hoff + t4A1 * 4];
        } else {
            b0r = *(const float4*)&Wo[(hoff + kB0) * 128 + j0 + j4B0 * 4];
            b1r = *(const float4*)&Wo[(hoff + kB1) * 128 + j0 + j4B1 * 4];
        }
        int ty4 = (tid >> 4) * 4, tx4 = (tid & 15) * 4;
        float acc[4][4] = {};
        for (int ch = 0; ch < 8; ch++) {
            __syncthreads();
            As[t4A0 * 4 + 0][iiA0] = a0r.x; As[t4A0 * 4 + 1][iiA0] = a0r.y;
            As[t4A0 * 4 + 2][iiA0] = a0r.z; As[t4A0 * 4 + 3][iiA0] = a0r.w;
            As[t4A1 * 4 + 0][iiA1] = a1r.x; As[t4A1 * 4 + 1][iiA1] = a1r.y;
            As[t4A1 * 4 + 2][iiA1] = a1r.z; As[t4A1 * 4 + 3][iiA1] = a1r.w;
            if (!doP) {
                Bs[t4A0 * 4 + 0][iiA0] = b0r.x; Bs[t4A0 * 4 + 1][iiA0] = b0r.y;
                Bs[t4A0 * 4 + 2][iiA0] = b0r.z; Bs[t4A0 * 4 + 3][iiA0] = b0r.w;
                Bs[t4A1 * 4 + 0][iiA1] = b1r.x; Bs[t4A1 * 4 + 1][iiA1] = b1r.y;
                Bs[t4A1 * 4 + 2][iiA1] = b1r.z; Bs[t4A1 * 4 + 3][iiA1] = b1r.w;
            } else {
                *(float4*)&Bs[kB0][j4B0 * 4] = b0r;
                *(float4*)&Bs[kB1][j4B1 * 4] = b1r;
            }
            __syncthreads();
            if (ch < 7) {
                int t0 = (ch + 1) * 32;
                a0r = *(const float4*)&Abase[(i0 + iiA0) * DTOT + hoff + t0 + t4A0 * 4];
                a1r = *(const float4*)&Abase[(i0 + iiA1) * DTOT + hoff + t0 + t4A1 * 4];
                if (!doP) {
                    b0r = *(const float4*)&Wk[(j0 + iiA0) * DTOT + hoff + t0 + t4A0 * 4];
                    b1r = *(const float4*)&Wk[(j0 + iiA1) * DTOT + hoff + t0 + t4A1 * 4];
                } else {
                    b0r = *(const float4*)&Wo[(hoff + t0 + kB0) * 128 + j0 + j4B0 * 4];
                    b1r = *(const float4*)&Wo[(hoff + t0 + kB1) * 128 + j0 + j4B1 * 4];
                }
            }
#pragma unroll
            for (int t = 0; t < 32; t++) {
                float4 a4 = *(const float4*)&As[t][ty4];
                float4 b4 = *(const float4*)&Bs[t][tx4];
                float av[4] = {a4.x, a4.y, a4.z, a4.w};
                float bv4[4] = {b4.x, b4.y, b4.z, b4.w};
#pragma unroll
                for (int u = 0; u < 4; u++)
#pragma unroll
                    for (int v = 0; v < 4; v++) acc[u][v] = fmaf(av[u], bv4[v], acc[u][v]);
            }
        }
        float* dst = doP ? g_P : g_M2;
#pragma unroll
        for (int u = 0; u < 4; u++) {
            float4 val = make_float4(acc[u][0], acc[u][1], acc[u][2], acc[u][3]);
            *(float4*)&dst[(h * 128 + i0 + ty4 + u) * 128 + j0 + tx4] = val;
        }
        return;
    }
    if (bid == 64) {
        __shared__ int ends[BATCHES];
        __shared__ int cnt[BATCHES];
        for (int i = tid; i < total; i += 256) {
            int bcur = batch[i];
            int bnxt = (i + 1 < total) ? batch[i + 1] : -1;
            if (bcur != bnxt) ends[bcur] = i + 1;
        }
        __syncthreads();
        if (tid < BATCHES) {
            int e = ends[tid];
            int s = (tid > 0) ? ends[tid - 1] : 0;
            g_start[tid] = s;
            cnt[tid] = e - s;
            g_cnt[tid] = e - s;
        }
        __syncthreads();
        if (tid < BATCHES) {
            int myc = cnt[tid];
            int rank = 0;
#pragma unroll 8
            for (int b = 0; b < BATCHES; b++) {
                int cb = cnt[b];
                rank += (cb > myc) || (cb == myc && b < tid);
            }
            g_order[rank] = tid;
        }
        return;
    }
    if (bid == 65) {
        int h = tid >> 5, lane = tid & 31;
        float s = 0.f;
#pragma unroll
        for (int q = 0; q < 8; q++) {
            int k = h * HIDDEN + lane + 32 * q;
            s = fmaf(bq[k], bk[k], s);
        }
#pragma unroll
        for (int o = 16; o; o >>= 1) s += __shfl_xor_sync(0xffffffffu, s, o);
        if (lane == 0) g_cc[h] = s;
        return;
    }
    if (bid < 322) {
        int gw = (bid - 66) * 8 + (tid >> 5);
        int lane = tid & 31;
        int which = gw >> 10;
        int h = (gw >> 7) & 7, i = gw & 127;
        const float* W  = which ? Wk : Wq;
        const float* bb = which ? bq : bk;
        float s = 0.f;
#pragma unroll
        for (int q = 0; q < 8; q++) {
            int k = lane + 32 * q;
            s = fmaf(W[i * DTOT + h * HIDDEN + k], bb[h * HIDDEN + k], s);
        }
#pragma unroll
        for (int o = 16; o; o >>= 1) s += __shfl_xor_sync(0xffffffffu, s, o);
        if (lane == 0) {
            if (which) g_w2[h][i] = s; else g_u[h][i] = s;
        }
        return;
    }
    {
        int p = bid - 322;
        int j = tid & 127;
        int half = tid >> 7;
        int k0 = p * 256 + half * 128;
        float s = 0.f;
#pragma unroll 8
        for (int kk = 0; kk < 128; kk++) {
            int k = k0 + kk;
            s = fmaf(bv[k], Wo[k * 128 + j], s);
        }
        g_cout_part[p * 2 + half][j] = s;
    }
}

// ---- out init ----
__global__ void k_init(float* __restrict__ out, const float* __restrict__ bo) {
    int b = blockIdx.x, j = threadIdx.x;
    float s = bo[j];
#pragma unroll
    for (int q = 0; q < 16; q++) s += g_cout_part[q][j];
    out[b * 128 + j] = 96.0f * s;
}

__global__ void k_nop() {}

// ======= fused attention (tf32, permuted-X layout for vector B loads) =======
// Xp[j][m'] with m' = (m&7)*12 + (m>>3): the 12 B-fragment values a thread
// needs per k-row are contiguous (m' = 12*lb + nt), m = 8*nt + lb.
#define XS 104
#define XT_FLOATS (128 * XS)
#define SMEM_FLOATS (2 * XT_FLOATS + 96 + 2*96 + 2*96 + 2*128 + 2*128 + 2*128)
#define SMEM_BYTES  (SMEM_FLOATS * 4)

__device__ __forceinline__ void mma_tf32(float c[4],
    uint32_t a0, uint32_t a1, uint32_t a2, uint32_t a3,
    uint32_t b0, uint32_t b1) {
    asm volatile(
        "mma.sync.aligned.m16n8k8.row.col.f32.tf32.tf32.f32 "
        "{%0,%1,%2,%3}, {%4,%5,%6,%7}, {%8,%9}, {%0,%1,%2,%3};\n"
        : "+f"(c[0]), "+f"(c[1]), "+f"(c[2]), "+f"(c[3])
        : "r"(a0), "r"(a1), "r"(a2), "r"(a3), "r"(b0), "r"(b1));
}

__device__ __forceinline__ void ld_brow(const float* __restrict__ row, float* b) {
    float4 v0 = ((const float4*)row)[0];
    float4 v1 = ((const float4*)row)[1];
    float4 v2 = ((const float4*)row)[2];
    b[0] = v0.x; b[1] = v0.y; b[2]  = v0.z; b[3]  = v0.w;
    b[4] = v1.x; b[5] = v1.y; b[6]  = v1.z; b[7]  = v1.w;
    b[8] = v2.x; b[9] = v2.y; b[10] = v2.z; b[11] = v2.w;
}

__global__ void __launch_bounds__(256, 2) k_attn(const float* __restrict__ X,
                                                 float* __restrict__ out) {
    int b = g_order[blockIdx.x];
    int h0 = blockIdx.y * 2;               // heads h0, h0+1
    int c = g_cnt[b];
    int st = g_start[b];
    float pcount = (float)(N_PAD - c);
    extern __shared__ float sm[];
    float* Xt = sm;                        // permuted X^T: Xp[j][m']
    float* Tt = sm + XT_FLOATS;            // stage / T [j][n] / S [n][m]
    float* sw = sm + 2 * XT_FLOATS;        // [96]
    float* qa = sw + 96;                   // [2][96]
    float* ka = qa + 192;                  // [2][96]
    float* us = ka + 192;                  // [2][128]
    float* ws = us + 256;                  // [2][128]
    float* zb = ws + 256;                  // [2][128]
    int tid = threadIdx.x;
    const int w = tid >> 5, lane = tid & 31;
    const int la = lane & 3, lb = lane >> 2;
    const int NT = (c + 7) >> 3;           // 4..12
    const int WS = (c + 15) >> 4;          // 2..6

    // ---- stage X f32 coalesced (stride 132) ----
    float4* stage4 = (float4*)Tt;
    for (int idx = tid; idx < c * 32; idx += 256) {
        int m = idx >> 5, l = idx & 31;
        stage4[m * 33 + l] = *(const float4*)&X[(st + m) * 128 + 4 * l];
    }
    if (tid < 128) { us[tid] = g_u[h0][tid];        ws[tid] = g_w2[h0][tid]; }
    else { us[tid] = g_u[h0 + 1][tid - 128];        ws[tid] = g_w2[h0 + 1][tid - 128]; }
    __syncthreads();

    // ---- bias terms for both heads ----
    if (tid < c) {
        const float4* xr = stage4 + tid * 33;
        const float4* u0 = (const float4*)us;
        const float4* u1 = (const float4*)(us + 128);
        const float4* w0 = (const float4*)ws;
        const float4* w1 = (const float4*)(ws + 128);
        float q0 = 0.f, k0 = 0.f, q1 = 0.f, k1 = 0.f;
#pragma unroll 4
        for (int j4 = 0; j4 < 32; j4++) {
            float4 xv = xr[j4];
            float4 a = u0[j4], bb = w0[j4], cc = u1[j4], dd = w1[j4];
            q0 = fmaf(xv.x, a.x, q0); k0 = fmaf(xv.x, bb.x, k0);
            q1 = fmaf(xv.x, cc.x, q1); k1 = fmaf(xv.x, dd.x, k1);
            q0 = fmaf(xv.y, a.y, q0); k0 = fmaf(xv.y, bb.y, k0);
            q1 = fmaf(xv.y, cc.y, q1); k1 = fmaf(xv.y, dd.y, k1);
            q0 = fmaf(xv.z, a.z, q0); k0 = fmaf(xv.z, bb.z, k0);
            q1 = fmaf(xv.z, cc.z, q1); k1 = fmaf(xv.z, dd.z, k1);
            q0 = fmaf(xv.w, a.w, q0); k0 = fmaf(xv.w, bb.w, k0);
            q1 = fmaf(xv.w, cc.w, q1); k1 = fmaf(xv.w, dd.w, k1);
        }
        qa[tid]       = SCALE * (q0 + g_cc[h0]);
        ka[tid]       = SCALE * k0;
        qa[96 + tid]  = SCALE * (q1 + g_cc[h0 + 1]);
        ka[96 + tid]  = SCALE * k1;
    }
    // ---- transpose stage -> Xp (permuted m', zero-pad m >= c) ----
    for (int idx = tid; idx < 128 * 96; idx += 256) {
        int j = idx / 96, m = idx - j * 96;
        int mp = (m & 7) * 12 + (m >> 3);
        Xt[j * XS + mp] = (m < c) ? Tt[m * 132 + j] : 0.f;
    }
    __syncthreads();

    for (int hh = 0; hh < 2; hh++) {
        const float* Mg = g_M2 + ((h0 + hh) << 14);
        const float* qah = qa + hh * 96;
        const float* kah = ka + hh * 96;

        // ---------- GEMM1: T[j][n] = sum_i M[i][j] X[n][i] ----------
        {
            float c1[12][4];
#pragma unroll
            for (int r = 0; r < 12; r++) { c1[r][0] = 0; c1[r][1] = 0; c1[r][2] = 0; c1[r][3] = 0; }
            uint32_t a0, a1, a2, a3, n0r, n1r, n2r, n3r;
            {
                const float* ap = Mg + la * 128 + 16 * w + lb;
                a0 = __float_as_uint(ap[0]);   a1 = __float_as_uint(ap[8]);
                a2 = __float_as_uint(ap[512]); a3 = __float_as_uint(ap[520]);
                const float* ap1 = Mg + (8 + la) * 128 + 16 * w + lb;
                n0r = __float_as_uint(ap1[0]);   n1r = __float_as_uint(ap1[8]);
                n2r = __float_as_uint(ap1[512]); n3r = __float_as_uint(ap1[520]);
            }
#pragma unroll
            for (int ks = 0; ks < 16; ks++) {
                uint32_t p0 = 0, p1 = 0, p2 = 0, p3 = 0;
                if (ks < 14) {
                    const float* ap = Mg + ((ks + 2) * 8 + la) * 128 + 16 * w + lb;
                    p0 = __float_as_uint(ap[0]);   p1 = __float_as_uint(ap[8]);
                    p2 = __float_as_uint(ap[512]); p3 = __float_as_uint(ap[520]);
                }
                float b0v[12], b1v[12];
                ld_brow(Xt + (ks * 8 + la) * XS + 12 * lb, b0v);
                ld_brow(Xt + (ks * 8 + la + 4) * XS + 12 * lb, b1v);
#pragma unroll
                for (int nt = 0; nt < 12; nt++) {
                    if (nt < NT)
                        mma_tf32(c1[nt], a0, a1, a2, a3,
                                 __float_as_uint(b0v[nt]), __float_as_uint(b1v[nt]));
                }
                a0 = n0r; a1 = n1r; a2 = n2r; a3 = n3r;
                n0r = p0; n1r = p1; n2r = p2; n3r = p3;
            }
            __syncthreads();     // head 1: softmax/z of head 0 done with Tt
            int r0 = 16 * w + lb;
#pragma unroll
            for (int nt = 0; nt < 12; nt++) {
                if (nt < NT) {
                    *(float2*)&Tt[r0 * XS + nt * 8 + 2 * la] = make_float2(c1[nt][0], c1[nt][1]);
                    *(float2*)&Tt[(r0 + 8) * XS + nt * 8 + 2 * la] = make_float2(c1[nt][2], c1[nt][3]);
                }
            }
        }
        __syncthreads();

        // ---------- GEMM2: S[n][m] = sum_j T[n][j] X[m][j]; warps < WS ----------
        float d[12][4];
#pragma unroll
        for (int r = 0; r < 12; r++) { d[r][0] = 0; d[r][1] = 0; d[r][2] = 0; d[r][3] = 0; }
        if (w < WS) {
#pragma unroll
            for (int ks = 0; ks < 16; ks++) {
                const float* tp = Tt + (ks * 8 + la) * XS + 16 * w + lb;
                uint32_t a0 = __float_as_uint(tp[0]);
                uint32_t a1 = __float_as_uint(tp[8]);
                uint32_t a2 = __float_as_uint(tp[4 * XS]);
                uint32_t a3 = __float_as_uint(tp[4 * XS + 8]);
                float b0v[12], b1v[12];
                ld_brow(Xt + (ks * 8 + la) * XS + 12 * lb, b0v);
                ld_brow(Xt + (ks * 8 + la + 4) * XS + 12 * lb, b1v);
#pragma unroll
                for (int mt = 0; mt < 12; mt++) {
                    if (mt < NT)
                        mma_tf32(d[mt], a0, a1, a2, a3,
                                 __float_as_uint(b0v[mt]), __float_as_uint(b1v[mt]));
                }
            }
        }
        __syncthreads();                      // Tt reads done before S overwrite
        float* Ss = Tt;                       // Ss[n][m] natural m order, stride XS
        if (w < WS) {
            int nr = 16 * w + lb;
#pragma unroll
            for (int mt = 0; mt < 12; mt++) {
                if (mt < NT) {
                    int mb = mt * 8 + 2 * la;
                    Ss[(nr    ) * XS + mb    ] = d[mt][0];
                    Ss[(nr    ) * XS + mb + 1] = d[mt][1];
                    Ss[(nr + 8) * XS + mb    ] = d[mt][2];
                    Ss[(nr + 8) * XS + mb + 1] = d[mt][3];
                }
            }
        }
        if (tid < 96) sw[tid] = (tid < c) ? pcount * (1.0f / 96.0f) : 0.f;
        __syncthreads();

        // ---------- fused softmax + key-mass ----------
        const int m0 = lane, m1 = lane + 32, m2 = lane + 64;
        const bool v0 = m0 < c, v1 = m1 < c, v2 = m2 < c;
        const float ka0 = v0 ? kah[m0] : 0.f;
        const float ka1 = v1 ? kah[m1] : 0.f;
        const float ka2 = v2 ? kah[m2] : 0.f;
        float aW0 = 0.f, aW1 = 0.f, aW2 = 0.f;
#pragma unroll
        for (int k = 0; k < 12; k++) {
            int n = w + 8 * k;
            if (n < c) {                       // warp-uniform
                float qan = qah[n];
                const float* Sr = Ss + n * XS;
                float e0 = v0 ? __expf(fmaf(SCALE, Sr[m0], qan + ka0)) : 0.f;
                float e1 = v1 ? __expf(fmaf(SCALE, Sr[m1], qan + ka1)) : 0.f;
                float e2 = v2 ? __expf(fmaf(SCALE, Sr[m2], qan + ka2)) : 0.f;
                float se = e0 + e1 + e2;
#pragma unroll
                for (int o = 16; o; o >>= 1) se += __shfl_xor_sync(0xffffffffu, se, o);
                se += pcount * __expf(qan);
                float iv = __fdividef(1.0f, se);
                aW0 = fmaf(e0, iv, aW0);
                aW1 = fmaf(e1, iv, aW1);
                aW2 = fmaf(e2, iv, aW2);
            }
        }
        if (v0) atomicAdd(&sw[m0], aW0);
        if (v1) atomicAdd(&sw[m1], aW1);
        if (v2) atomicAdd(&sw[m2], aW2);
        __syncthreads();

        // ---------- z[i] = sum_m sw[m] * x_m[i]  (permuted column read) ----------
        {
            bool u1v = lane + 32 < c, u2v = lane + 64 < c;
            float s0 = (lane < c) ? sw[lane] : 0.f;
            float s1 = u1v ? sw[lane + 32] : 0.f;
            float s2 = u2v ? sw[lane + 64] : 0.f;
            int mp0 = (lane & 7) * 12 + (lane >> 3);   // perm(lane); +4/+8 for +32/+64
#pragma unroll
            for (int q = 0; q < 16; q++) {
                int i = w + 8 * q;
                const float* Xr = Xt + i * XS;
                float part = s0 * Xr[mp0];
                part = fmaf(s1, Xr[mp0 + 4], part);
                part = fmaf(s2, Xr[mp0 + 8], part);
#pragma unroll
                for (int o = 16; o; o >>= 1) part += __shfl_xor_sync(0xffffffffu, part, o);
                if (lane == 0) zb[hh * 128 + i] = part;
            }
        }
        __syncthreads();
    }

    // ---------- fused output ----------
    {
        int half = tid >> 7, j = tid & 127;
        const float* Pp = g_P + ((h0 + half) << 14) + j;
        const float* zp = zb + half * 128;
        float a0 = 0.f, a1 = 0.f, a2 = 0.f, a3 = 0.f;
#pragma unroll
        for (int i = 0; i < 128; i += 4) {
            a0 = fmaf(zp[i    ], Pp[(i    ) * 128], a0);
            a1 = fmaf(zp[i + 1], Pp[(i + 1) * 128], a1);
            a2 = fmaf(zp[i + 2], Pp[(i + 2) * 128], a2);
            a3 = fmaf(zp[i + 3], Pp[(i + 3) * 128], a3);
        }
        atomicAdd(&out[b * 128 + j], (a0 + a1) + (a2 + a3));
    }
}

// ================= launch =================
extern "C" void kernel_launch(void* const* d_in, const int* in_sizes, int n_in,
                              void* d_out, int out_size) {
    const float* x     = (const float*)d_in[0];
    const int*   batch = (const int*)  d_in[1];
    const float* Wq    = (const float*)d_in[2];
    const float* bq    = (const float*)d_in[3];
    const float* Wk    = (const float*)d_in[4];
    const float* bk    = (const float*)d_in[5];
    const float* Wv    = (const float*)d_in[6];
    const float* bv    = (const float*)d_in[7];
    const float* Wo    = (const float*)d_in[8];
    const float* bo    = (const float*)d_in[9];
    float* out = (float*)d_out;
    int total = in_sizes[1];

    cudaFuncSetAttribute(k_attn, cudaFuncAttributeMaxDynamicSharedMemorySize, SMEM_BYTES);

    k_prep<<<330, 256>>>(batch, Wq, bq, Wk, bk, Wv, bv, Wo, bo, total);
    k_init<<<BATCHES, 128>>>(out, bo);
    k_nop<<<1, 32>>>();
    k_attn<<<dim3(BATCHES, 4), 256, SMEM_BYTES>>>(x, out);
}